// round 14
// baseline (speedup 1.0000x reference)
#include <cuda_runtime.h>
#include <math.h>

#define E_DIM 1280
#define NHEAD 20
#define DHEAD 64
#define T_TOK 8192
#define SEQ   1024
#define NBATCH 8

// ---------------- scratch (no allocations allowed) ----------------
__device__ float g_h[T_TOK * E_DIM];
__device__ float g_q[T_TOK * E_DIM];
__device__ float g_k[T_TOK * E_DIM];
__device__ float g_v[T_TOK * E_DIM];
__device__ float g_o[T_TOK * E_DIM];
__device__ float g_wq[E_DIM * E_DIM];
__device__ float g_wk[E_DIM * E_DIM];
__device__ float g_wv[E_DIM * E_DIM];
__device__ float g_wo[E_DIM * E_DIM];
__device__ float g_cos[T_TOK * 32];
__device__ float g_sin[T_TOK * 32];

// ---------------- helpers ----------------
__device__ __forceinline__ unsigned f2tf(float f) {
    unsigned u;
    asm("cvt.rna.tf32.f32 %0, %1;" : "=r"(u) : "f"(f));
    return u;
}
__device__ __forceinline__ float f2tff(float f) {
    return __uint_as_float(f2tf(f));
}

__device__ __forceinline__ void mma_tf32(float c[4], const unsigned a[4],
                                         unsigned b0, unsigned b1) {
    asm volatile(
        "mma.sync.aligned.m16n8k8.row.col.f32.tf32.tf32.f32 "
        "{%0,%1,%2,%3}, {%4,%5,%6,%7}, {%8,%9}, {%0,%1,%2,%3};\n"
        : "+f"(c[0]), "+f"(c[1]), "+f"(c[2]), "+f"(c[3])
        : "r"(a[0]), "r"(a[1]), "r"(a[2]), "r"(a[3]), "r"(b0), "r"(b1));
}

__device__ __forceinline__ void cpa16(void* s, const void* g) {
    unsigned saddr = (unsigned)__cvta_generic_to_shared(s);
    asm volatile("cp.async.ca.shared.global [%0], [%1], 16;\n"
                 :: "r"(saddr), "l"(g));
}
#define CP_COMMIT() asm volatile("cp.async.commit_group;\n" ::: "memory")
#define CP_WAIT(N)  asm volatile("cp.async.wait_group " #N ";\n" ::: "memory")

// ------------- weight prep: round to tf32 in global ---------------
__global__ void __launch_bounds__(256) wprep_kernel(
    const float* __restrict__ Wq, const float* __restrict__ Wk,
    const float* __restrict__ Wv, const float* __restrict__ Wo)
{
    const float* src = (blockIdx.y == 0) ? Wq : (blockIdx.y == 1) ? Wk :
                       (blockIdx.y == 2) ? Wv : Wo;
    float* dst = (blockIdx.y == 0) ? g_wq : (blockIdx.y == 1) ? g_wk :
                 (blockIdx.y == 2) ? g_wv : g_wo;
    int i = (blockIdx.x * 256 + threadIdx.x) * 4;
    float4 v = *(const float4*)&src[i];
    *(float4*)&dst[i] = make_float4(f2tff(v.x), f2tff(v.y), f2tff(v.z), f2tff(v.w));
}

// ---------------- LayerNorm (with bias) : x -> h (tf32-rounded) ----
__global__ void __launch_bounds__(256) ln_kernel(
    const float* __restrict__ x, const float* __restrict__ w,
    const float* __restrict__ b, float* __restrict__ out)
{
    int t = blockIdx.x;
    const float* xr = x + (size_t)t * E_DIM;
    float vals[5];
    float s = 0.f, s2 = 0.f;
#pragma unroll
    for (int j = 0; j < 5; j++) {
        float v = xr[threadIdx.x + j * 256];
        vals[j] = v; s += v; s2 += v * v;
    }
    __shared__ float red0[8], red1[8];
    int lane = threadIdx.x & 31, wid = threadIdx.x >> 5;
#pragma unroll
    for (int o = 16; o; o >>= 1) {
        s  += __shfl_xor_sync(0xffffffffu, s,  o);
        s2 += __shfl_xor_sync(0xffffffffu, s2, o);
    }
    if (lane == 0) { red0[wid] = s; red1[wid] = s2; }
    __syncthreads();
    float ts = 0.f, ts2 = 0.f;
#pragma unroll
    for (int j = 0; j < 8; j++) { ts += red0[j]; ts2 += red1[j]; }
    float mean = ts * (1.f / E_DIM);
    float var  = ts2 * (1.f / E_DIM) - mean * mean;
    float rstd = rsqrtf(var + 1e-5f);
    float* orow = out + (size_t)t * E_DIM;
#pragma unroll
    for (int j = 0; j < 5; j++) {
        int idx = threadIdx.x + j * 256;
        orow[idx] = f2tff((vals[j] - mean) * rstd * w[idx] + b[idx]);
    }
}

// ---------------- RoPE table: cos/sin per (token, freq) ------------
__global__ void __launch_bounds__(256) rope_table_kernel(
    const int* __restrict__ cu, int nb)
{
    int t = blockIdx.x * 8 + (threadIdx.x >> 5);
    int f = threadIdx.x & 31;
    int seg = 0;
    for (int bb = 1; bb < nb; bb++) if (t >= cu[bb]) seg = bb;
    float pos = (float)(t - cu[seg]);
    const float kfreq = -0.2878231366f; // -ln(10000)/32
    float ang = pos * __expf((float)f * kfreq);
    float sn, c;
    sincosf(ang, &sn, &c);
    g_cos[t * 32 + f] = c;
    g_sin[t * 32 + f] = sn;
}

// ------------- LayerNorm (no bias) + RoPE, in place (rounded) ------
__global__ void __launch_bounds__(256) lnrope_kernel(
    float* __restrict__ q, float* __restrict__ k,
    const float* __restrict__ wq, const float* __restrict__ wk)
{
    int t = blockIdx.x;
    int part = blockIdx.y;
    __shared__ float sb[E_DIM];
    __shared__ float red0[8], red1[8];
    __shared__ float s_stats[2];
    int lane = threadIdx.x & 31, wid = threadIdx.x >> 5;

    float* base = (part ? k : q) + (size_t)t * E_DIM;
    const float* w = part ? wk : wq;
    float s = 0.f, s2 = 0.f;
    for (int i = threadIdx.x; i < E_DIM; i += 256) {
        float v = base[i];
        sb[i] = v; s += v; s2 += v * v;
    }
#pragma unroll
    for (int o = 16; o; o >>= 1) {
        s  += __shfl_xor_sync(0xffffffffu, s,  o);
        s2 += __shfl_xor_sync(0xffffffffu, s2, o);
    }
    if (lane == 0) { red0[wid] = s; red1[wid] = s2; }
    __syncthreads();
    if (threadIdx.x == 0) {
        float ts = 0.f, ts2 = 0.f;
#pragma unroll
        for (int j = 0; j < 8; j++) { ts += red0[j]; ts2 += red1[j]; }
        float mean = ts * (1.f / E_DIM);
        float var  = ts2 * (1.f / E_DIM) - mean * mean;
        s_stats[0] = mean;
        s_stats[1] = rsqrtf(var + 1e-5f);
    }
    __syncthreads();
    float mean = s_stats[0], rstd = s_stats[1];
    for (int i = threadIdx.x; i < E_DIM; i += 256) {
        int ld = i & 63;
        float xn = (sb[i] - mean) * rstd * w[i];
        int pi = (ld < 32) ? (i + 32) : (i - 32);
        float pn = (sb[pi] - mean) * rstd * w[pi];
        int fi = ld & 31;
        float c  = g_cos[t * 32 + fi];
        float sn = g_sin[t * 32 + fi];
        float rot = (ld < 32) ? -pn : pn;
        base[i] = f2tff(xn * c + rot * sn);
    }
}

// ------------- tf32 GEMM core, 3-stage cp.async pipeline -----------
// 128 threads (4 warps, 2x2), warp tile 64x64, 3 CTAs/SM. (R12 passing)
#define GSTR 20
#define GSTAGE_F (2 * 128 * GSTR)            // floats per stage (A then B)
#define GEMM_SMEM_BYTES (3 * GSTAGE_F * 4)   // 61440

__device__ __forceinline__ void gemm_body(
    const float* __restrict__ A, const float* __restrict__ B,
    float* __restrict__ C, int bm, int bn, int N, int K,
    float* sd, bool rnd)
{
    int tid = threadIdx.x, lane = tid & 31, warp = tid >> 5;
    int gid = lane >> 2, tig = lane & 3;
    int wm = (warp >> 1) * 64, wn = (warp & 1) * 64;

    float acc[4][8][4];
#pragma unroll
    for (int i = 0; i < 4; i++)
#pragma unroll
        for (int j = 0; j < 8; j++)
#pragma unroll
            for (int l = 0; l < 4; l++) acc[i][j][l] = 0.f;

    int lr = tid >> 2;           // 0..31
    int lc = (tid & 3) << 2;     // 0,4,8,12
    const float* Ap = A + (size_t)(bm + lr) * K + lc;
    const float* Bp = B + (size_t)(bn + lr) * K + lc;

#define ISSUE(S, K0) { \
    int s_ = (S); int k0_ = (K0); \
    float* As_ = sd + s_ * GSTAGE_F; \
    float* Bs_ = As_ + 128 * GSTR; \
    _Pragma("unroll") \
    for (int ii = 0; ii < 4; ii++) { \
        int row = lr + ii * 32; \
        cpa16(&As_[row * GSTR + lc], Ap + (size_t)ii * 32 * K + k0_); \
        cpa16(&Bs_[row * GSTR + lc], Bp + (size_t)ii * 32 * K + k0_); \
    } }

#define COMPUTE(S) { \
    const float* Asb = sd + (S) * GSTAGE_F; \
    const float* Bsb = Asb + 128 * GSTR; \
    _Pragma("unroll") \
    for (int ks = 0; ks < 2; ks++) { \
        unsigned af[4][4]; \
        _Pragma("unroll") \
        for (int mf = 0; mf < 4; mf++) { \
            int base = (wm + mf * 16 + gid) * GSTR + ks * 8 + tig; \
            af[mf][0] = __float_as_uint(Asb[base]); \
            af[mf][1] = __float_as_uint(Asb[base + 8 * GSTR]); \
            af[mf][2] = __float_as_uint(Asb[base + 4]); \
            af[mf][3] = __float_as_uint(Asb[base + 8 * GSTR + 4]); \
        } \
        _Pragma("unroll") \
        for (int nf = 0; nf < 8; nf++) { \
            int bb = (wn + nf * 8 + gid) * GSTR + ks * 8 + tig; \
            unsigned b0 = __float_as_uint(Bsb[bb]); \
            unsigned b1 = __float_as_uint(Bsb[bb + 4]); \
            mma_tf32(acc[0][nf], af[0], b0, b1); \
            mma_tf32(acc[1][nf], af[1], b0, b1); \
            mma_tf32(acc[2][nf], af[2], b0, b1); \
            mma_tf32(acc[3][nf], af[3], b0, b1); \
        } \
    } }

    int NT = K / 16;   // 80
    ISSUE(0, 0);  CP_COMMIT();
    ISSUE(1, 16); CP_COMMIT();
    int cs = 0;        // compute stage = i % 3
    for (int i = 0; i < NT; i++) {
        CP_WAIT(1);
        __syncthreads();
        COMPUTE(cs);
        if (i + 2 < NT) {
            int ns = cs - 1; if (ns < 0) ns = 2;   // (i+2)%3
            ISSUE(ns, (i + 2) * 16);
        }
        CP_COMMIT();   // empty groups at tail keep the wait count uniform
        cs = (cs == 2) ? 0 : cs + 1;
    }

#pragma unroll
    for (int mf = 0; mf < 4; mf++)
#pragma unroll
        for (int nf = 0; nf < 8; nf++) {
            int row = bm + wm + mf * 16 + gid;
            int col = bn + wn + nf * 8 + 2 * tig;
            float v0 = acc[mf][nf][0], v1 = acc[mf][nf][1];
            float v2 = acc[mf][nf][2], v3 = acc[mf][nf][3];
            if (rnd) { v0 = f2tff(v0); v1 = f2tff(v1); v2 = f2tff(v2); v3 = f2tff(v3); }
            *(float2*)&C[(size_t)row * N + col] = make_float2(v0, v1);
            *(float2*)&C[(size_t)(row + 8) * N + col] = make_float2(v2, v3);
        }
#undef ISSUE
#undef COMPUTE
}

// Merged QKV projection: grid (30, 64); v output tf32-rounded.
__global__ void __launch_bounds__(128, 3) gemm_qkv(
    const float* __restrict__ A,
    float* __restrict__ q, float* __restrict__ k, float* __restrict__ v)
{
    extern __shared__ float sd[];
    int which = blockIdx.x / 10;
    int bn = (blockIdx.x % 10) * 128;
    int bm = blockIdx.y * 128;
    const float* B = (which == 0) ? g_wq : (which == 1) ? g_wk : g_wv;
    float* C = (which == 0) ? q : (which == 1) ? k : v;
    gemm_body(A, B, C, bm, bn, E_DIM, E_DIM, sd, which == 2);
}

// Single GEMM (output projection), B = g_wo, unrounded output
__global__ void __launch_bounds__(128, 3) gemm_one(
    const float* __restrict__ A, float* __restrict__ C)
{
    extern __shared__ float sd[];
    gemm_body(A, g_wo, C, blockIdx.y * 128, blockIdx.x * 128, E_DIM, E_DIM,
              sd, false);
}

// ------------- flash attention, tf32 TC, register-resident P -------
// 128 q-rows/CTA, 4 warps x 32 rows. P never touches smem: the QK
// accumulator (rows {gid,gid+8} x cols {2tig,2tig+1}) is permuted to
// the PV A-fragment layout (k in {tig,tig+4}) via intra-quad shuffles
// (src lane keeps gid bits). Smem = K/V double buffer only (71.7KB).
#define KS_STRIDE 68
#define VS_STRIDE 72
#define ATT_STAGE_F (64 * KS_STRIDE + 64 * VS_STRIDE)   // 8960 floats
#define ATT_SMEM_BYTES (2 * ATT_STAGE_F * 4)            // 71680

__global__ void __launch_bounds__(128) attn_tf32(
    const float* __restrict__ q, const float* __restrict__ k,
    const float* __restrict__ v, float* __restrict__ o)
{
    extern __shared__ float sm[];

    int b = blockIdx.z, h = blockIdx.y, qt = blockIdx.x;
    int tid = threadIdx.x;
    int warp = tid >> 5, lane = tid & 31;
    int gid = lane >> 2, tig = lane & 3;
    int m0 = warp * 32;
    int tq0 = b * SEQ + qt * 128;
    int srcA = (lane & 28) | (tig >> 1);
    int srcB = srcA | 2;
    bool odd = (tig & 1) != 0;

#define ATT_ISSUE(KT, S) { \
    int kt_ = (KT); int s_ = (S); \
    float* Ks_ = sm + s_ * ATT_STAGE_F; \
    float* Vs_ = Ks_ + 64 * KS_STRIDE; \
    int tk0_ = b * SEQ + kt_ * 64; \
    _Pragma("unroll") \
    for (int ii = 0; ii < 8; ii++) { \
        int idx_ = tid + ii * 128; \
        int r_ = idx_ >> 4, c4_ = (idx_ & 15) << 2; \
        const size_t goff_ = (size_t)(tk0_ + r_) * E_DIM + h * 64 + c4_; \
        cpa16(&Ks_[r_ * KS_STRIDE + c4_], &k[goff_]); \
        cpa16(&Vs_[r_ * VS_STRIDE + c4_], &v[goff_]); \
    } }

    ATT_ISSUE(0, 0); CP_COMMIT();

    unsigned qf[8][2][4];
#pragma unroll
    for (int mf = 0; mf < 2; mf++) {
        const float* qp = q + (size_t)(tq0 + m0 + mf * 16 + gid) * E_DIM + h * 64;
#pragma unroll
        for (int ks = 0; ks < 8; ks++) {
            int c = ks * 8 + tig;
            qf[ks][mf][0] = f2tf(qp[c] * 0.125f);
            qf[ks][mf][1] = f2tf(qp[(size_t)8 * E_DIM + c] * 0.125f);
            qf[ks][mf][2] = f2tf(qp[c + 4] * 0.125f);
            qf[ks][mf][3] = f2tf(qp[(size_t)8 * E_DIM + c + 4] * 0.125f);
        }
    }

    float mrow[2][2], lrow[2][2];
#pragma unroll
    for (int mf = 0; mf < 2; mf++) {
        mrow[mf][0] = -1e30f; mrow[mf][1] = -1e30f;
        lrow[mf][0] = 0.f;    lrow[mf][1] = 0.f;
    }
    float oc[2][8][4];
#pragma unroll
    for (int mf = 0; mf < 2; mf++)
#pragma unroll
        for (int j = 0; j < 8; j++)
#pragma unroll
            for (int l = 0; l < 4; l++) oc[mf][j][l] = 0.f;

    for (int kt = 0; kt < SEQ / 64; kt++) {
        int cur = kt & 1;
        float* Ks = sm + cur * ATT_STAGE_F;
        float* Vs = Ks + 64 * KS_STRIDE;

        CP_WAIT(0);          // tile kt landed
        __syncthreads();     // visibility + WAR fence for this buffer

        // ---- QK^T: S[32 x 64] per warp ----
        float sc[2][8][4];
#pragma unroll
        for (int mf = 0; mf < 2; mf++)
#pragma unroll
            for (int j = 0; j < 8; j++)
#pragma unroll
                for (int l = 0; l < 4; l++) sc[mf][j][l] = 0.f;
#pragma unroll
        for (int ks = 0; ks < 8; ks++) {
#pragma unroll
            for (int nf = 0; nf < 8; nf++) {
                int bb = (nf * 8 + gid) * KS_STRIDE + ks * 8 + tig;
                unsigned b0 = __float_as_uint(Ks[bb]);
                unsigned b1 = __float_as_uint(Ks[bb + 4]);
                mma_tf32(sc[0][nf], qf[ks][0], b0, b1);
                mma_tf32(sc[1][nf], qf[ks][1], b0, b1);
            }
        }

        // ---- online softmax + in-register transpose to A fragments ----
        unsigned pa[2][8][4];
#pragma unroll
        for (int mf = 0; mf < 2; mf++) {
            float tm0 = -1e30f, tm1 = -1e30f;
#pragma unroll
            for (int nf = 0; nf < 8; nf++) {
                tm0 = fmaxf(tm0, fmaxf(sc[mf][nf][0], sc[mf][nf][1]));
                tm1 = fmaxf(tm1, fmaxf(sc[mf][nf][2], sc[mf][nf][3]));
            }
            tm0 = fmaxf(tm0, __shfl_xor_sync(0xffffffffu, tm0, 1));
            tm0 = fmaxf(tm0, __shfl_xor_sync(0xffffffffu, tm0, 2));
            tm1 = fmaxf(tm1, __shfl_xor_sync(0xffffffffu, tm1, 1));
            tm1 = fmaxf(tm1, __shfl_xor_sync(0xffffffffu, tm1, 2));
            float mn0 = fmaxf(mrow[mf][0], tm0), mn1 = fmaxf(mrow[mf][1], tm1);
            float cor0 = __expf(mrow[mf][0] - mn0);
            float cor1 = __expf(mrow[mf][1] - mn1);
            float ls0 = 0.f, ls1 = 0.f;
#pragma unroll
            for (int nf = 0; nf < 8; nf++) {
                float p0 = __expf(sc[mf][nf][0] - mn0);
                float p1 = __expf(sc[mf][nf][1] - mn0);
                float p2 = __expf(sc[mf][nf][2] - mn1);
                float p3 = __expf(sc[mf][nf][3] - mn1);
                ls0 += p0 + p1; ls1 += p2 + p3;
                // rounded tf32 bits (same rounding site as the old smem P)
                unsigned q0 = f2tf(p0), q1 = f2tf(p1);
                unsigned q2 = f2tf(p2), q3 = f2tf(p3);
                // permute: col tig from pair (2*(tig>>1), +1) of lane srcA;
                // col tig+4 from lane srcB. gid bits preserved -> same rows.
                unsigned e0 = __shfl_sync(0xffffffffu, q0, srcA);
                unsigned o0 = __shfl_sync(0xffffffffu, q1, srcA);
                unsigned e1 = __shfl_sync(0xffffffffu, q2, srcA);
                unsigned o1 = __shfl_sync(0xffffffffu, q3, srcA);
                unsigned e2 = __shfl_sync(0xffffffffu, q0, srcB);
                unsigned o2 = __shfl_sync(0xffffffffu, q1, srcB);
                unsigned e3 = __shfl_sync(0xffffffffu, q2, srcB);
                unsigned o3 = __shfl_sync(0xffffffffu, q3, srcB);
                pa[mf][nf][0] = odd ? o0 : e0;   // (gid,   k=tig)
                pa[mf][nf][1] = odd ? o1 : e1;   // (gid+8, k=tig)
                pa[mf][nf][2] = odd ? o2 : e2;   // (gid,   k=tig+4)
                pa[mf][nf][3] = odd ? o3 : e3;   // (gid+8, k=tig+4)
            }
            ls0 += __shfl_xor_sync(0xffffffffu, ls0, 1);
            ls0 += __shfl_xor_sync(0xffffffffu, ls0, 2);
            ls1 += __shfl_xor_sync(0xffffffffu, ls1, 1);
            ls1 += __shfl_xor_sync(0xffffffffu, ls1, 2);
            lrow[mf][0] = lrow[mf][0] * cor0 + ls0;
            lrow[mf][1] = lrow[mf][1] * cor1 + ls1;
            mrow[mf][0] = mn0; mrow[mf][1] = mn1;
#pragma unroll
            for (int nf = 0; nf < 8; nf++) {
                oc[mf][nf][0] *= cor0; oc[mf][nf][1] *= cor0;
                oc[mf][nf][2] *= cor1; oc[mf][nf][3] *= cor1;
            }
        }

        // ---- PV: O[32 x 64] += P[32 x 64k] * V[64k x 64] ----
#pragma unroll
        for (int ks = 0; ks < 8; ks++) {
#pragma unroll
            for (int nf = 0; nf < 8; nf++) {
                int vb = (ks * 8 + tig) * VS_STRIDE + nf * 8 + gid;
                unsigned b0 = __float_as_uint(Vs[vb]);
                unsigned b1 = __float_as_uint(Vs[vb + 4 * VS_STRIDE]);
                mma_tf32(oc[0][nf], pa[0][ks], b0, b1);
                mma_tf32(oc[1][nf], pa[1][ks], b0, b1);
            }
        }

        // prefetch next tile into the other buffer: all warps passed the
        // top-of-kt barrier, so their kt-1 reads of that buffer are done.
        if (kt + 1 < SEQ / 64) { ATT_ISSUE(kt + 1, 1 - cur); }
        CP_COMMIT();
    }

    // o written tf32-rounded -> Wout GEMM reads raw bits
#pragma unroll
    for (int mf = 0; mf < 2; mf++) {
        float il0 = 1.f / lrow[mf][0], il1 = 1.f / lrow[mf][1];
        int row = tq0 + m0 + mf * 16 + gid;
#pragma unroll
        for (int nf = 0; nf < 8; nf++) {
            int col = h * 64 + nf * 8 + 2 * tig;
            *(float2*)&o[(size_t)row * E_DIM + col] =
                make_float2(f2tff(oc[mf][nf][0] * il0), f2tff(oc[mf][nf][1] * il0));
            *(float2*)&o[(size_t)(row + 8) * E_DIM + col] =
                make_float2(f2tff(oc[mf][nf][2] * il1), f2tff(oc[mf][nf][3] * il1));
        }
    }
#undef ATT_ISSUE
}

// -------------------------------------------------------------------
extern "C" void kernel_launch(void* const* d_in, const int* in_sizes, int n_in,
                              void* d_out, int out_size)
{
    const float* x  = (const float*)d_in[0];
    const int*   cu = (const int*)d_in[1];
    int idx = 2;
    if (in_sizes[2] == 1) idx = 3;  // skip scalar max_len if present
    const float* norm_w = (const float*)d_in[idx++];
    const float* norm_b = (const float*)d_in[idx++];
    const float* Wq     = (const float*)d_in[idx++];
    const float* Wk     = (const float*)d_in[idx++];
    const float* Wv     = (const float*)d_in[idx++];
    const float* Wout   = (const float*)d_in[idx++];
    const float* lnq_w  = (const float*)d_in[idx++];
    const float* lnk_w  = (const float*)d_in[idx++];
    float* out = (float*)d_out;

    int nb = in_sizes[1] - 1;

    float *h, *q, *k, *v, *o;
    cudaGetSymbolAddress((void**)&h, g_h);
    cudaGetSymbolAddress((void**)&q, g_q);
    cudaGetSymbolAddress((void**)&k, g_k);
    cudaGetSymbolAddress((void**)&v, g_v);
    cudaGetSymbolAddress((void**)&o, g_o);

    cudaFuncSetAttribute(gemm_qkv, cudaFuncAttributeMaxDynamicSharedMemorySize,
                         GEMM_SMEM_BYTES);
    cudaFuncSetAttribute(gemm_one, cudaFuncAttributeMaxDynamicSharedMemorySize,
                         GEMM_SMEM_BYTES);
    cudaFuncSetAttribute(attn_tf32, cudaFuncAttributeMaxDynamicSharedMemorySize,
                         ATT_SMEM_BYTES);

    // 0) round weights to tf32 once per call
    wprep_kernel<<<dim3(E_DIM * E_DIM / 1024, 4), 256>>>(Wq, Wk, Wv, Wout);

    // 1) pre-norm (tf32-rounded output) + rope table
    ln_kernel<<<T_TOK, 256>>>(x, norm_w, norm_b, h);
    rope_table_kernel<<<T_TOK / 8, 256>>>(cu, nb);

    // 2) merged Q/K/V projections (3-stage pipeline, 3 CTAs/SM)
    gemm_qkv<<<dim3(30, T_TOK / 128), 128, GEMM_SMEM_BYTES>>>(h, q, k, v);

    // 3) q/k LayerNorm + RoPE (in place, rounded output)
    lnrope_kernel<<<dim3(T_TOK, 2), 256>>>(q, k, lnq_w, lnk_w);

    // 4) attention (register-resident P, double-buffered K/V)
    dim3 agrid(SEQ / 128, NHEAD, NBATCH);
    attn_tf32<<<agrid, 128, ATT_SMEM_BYTES>>>(q, k, v, o);

    // 5) output projection
    gemm_one<<<dim3(E_DIM / 128, T_TOK / 128), 128, GEMM_SMEM_BYTES>>>(o, out);
}

// round 15
// speedup vs baseline: 1.2969x; 1.2969x over previous
#include <cuda_runtime.h>
#include <cuda_fp16.h>
#include <math.h>

#define E_DIM 1280
#define NHEAD 20
#define DHEAD 64
#define T_TOK 8192
#define SEQ   1024
#define NBATCH 8

// ---------------- scratch (no allocations allowed) ----------------
__device__ __half g_hh[T_TOK * E_DIM];     // LN output (fp16)
__device__ float  g_q[T_TOK * E_DIM];
__device__ float  g_k[T_TOK * E_DIM];
__device__ float  g_v[T_TOK * E_DIM];
__device__ __half g_oh[T_TOK * E_DIM];     // attention output (fp16)
__device__ __half g_wqh[E_DIM * E_DIM];
__device__ __half g_wkh[E_DIM * E_DIM];
__device__ __half g_wvh[E_DIM * E_DIM];
__device__ __half g_woh[E_DIM * E_DIM];
__device__ float  g_cos[T_TOK * 32];
__device__ float  g_sin[T_TOK * 32];

// ---------------- helpers ----------------
__device__ __forceinline__ unsigned f2tf(float f) {
    unsigned u;
    asm("cvt.rna.tf32.f32 %0, %1;" : "=r"(u) : "f"(f));
    return u;
}
__device__ __forceinline__ float f2tff(float f) {
    return __uint_as_float(f2tf(f));
}

__device__ __forceinline__ void mma_tf32(float c[4], const unsigned a[4],
                                         unsigned b0, unsigned b1) {
    asm volatile(
        "mma.sync.aligned.m16n8k8.row.col.f32.tf32.tf32.f32 "
        "{%0,%1,%2,%3}, {%4,%5,%6,%7}, {%8,%9}, {%0,%1,%2,%3};\n"
        : "+f"(c[0]), "+f"(c[1]), "+f"(c[2]), "+f"(c[3])
        : "r"(a[0]), "r"(a[1]), "r"(a[2]), "r"(a[3]), "r"(b0), "r"(b1));
}

__device__ __forceinline__ void mma_f16(float c[4], const unsigned a[4],
                                        unsigned b0, unsigned b1) {
    asm volatile(
        "mma.sync.aligned.m16n8k16.row.col.f32.f16.f16.f32 "
        "{%0,%1,%2,%3}, {%4,%5,%6,%7}, {%8,%9}, {%0,%1,%2,%3};\n"
        : "+f"(c[0]), "+f"(c[1]), "+f"(c[2]), "+f"(c[3])
        : "r"(a[0]), "r"(a[1]), "r"(a[2]), "r"(a[3]), "r"(b0), "r"(b1));
}

__device__ __forceinline__ void cpa16(void* s, const void* g) {
    unsigned saddr = (unsigned)__cvta_generic_to_shared(s);
    asm volatile("cp.async.ca.shared.global [%0], [%1], 16;\n"
                 :: "r"(saddr), "l"(g));
}
__device__ __forceinline__ void cpa16u(unsigned saddr, const void* g) {
    asm volatile("cp.async.ca.shared.global [%0], [%1], 16;\n"
                 :: "r"(saddr), "l"(g));
}
#define CP_COMMIT() asm volatile("cp.async.commit_group;\n" ::: "memory")
#define CP_WAIT(N)  asm volatile("cp.async.wait_group " #N ";\n" ::: "memory")

// ------------- weight prep: round to fp16 in global ---------------
__global__ void __launch_bounds__(256) wprep_kernel(
    const float* __restrict__ Wq, const float* __restrict__ Wk,
    const float* __restrict__ Wv, const float* __restrict__ Wo)
{
    const float* src = (blockIdx.y == 0) ? Wq : (blockIdx.y == 1) ? Wk :
                       (blockIdx.y == 2) ? Wv : Wo;
    __half* dst = (blockIdx.y == 0) ? g_wqh : (blockIdx.y == 1) ? g_wkh :
                  (blockIdx.y == 2) ? g_wvh : g_woh;
    int i = (blockIdx.x * 256 + threadIdx.x) * 4;
    float4 v = *(const float4*)&src[i];
    *(__half2*)&dst[i]     = __floats2half2_rn(v.x, v.y);
    *(__half2*)&dst[i + 2] = __floats2half2_rn(v.z, v.w);
}

// ---------------- LayerNorm (with bias) : x -> h (fp16) ------------
__global__ void __launch_bounds__(256) ln_kernel(
    const float* __restrict__ x, const float* __restrict__ w,
    const float* __restrict__ b, __half* __restrict__ out)
{
    int t = blockIdx.x;
    const float* xr = x + (size_t)t * E_DIM;
    float vals[5];
    float s = 0.f, s2 = 0.f;
#pragma unroll
    for (int j = 0; j < 5; j++) {
        float v = xr[threadIdx.x + j * 256];
        vals[j] = v; s += v; s2 += v * v;
    }
    __shared__ float red0[8], red1[8];
    int lane = threadIdx.x & 31, wid = threadIdx.x >> 5;
#pragma unroll
    for (int o = 16; o; o >>= 1) {
        s  += __shfl_xor_sync(0xffffffffu, s,  o);
        s2 += __shfl_xor_sync(0xffffffffu, s2, o);
    }
    if (lane == 0) { red0[wid] = s; red1[wid] = s2; }
    __syncthreads();
    float ts = 0.f, ts2 = 0.f;
#pragma unroll
    for (int j = 0; j < 8; j++) { ts += red0[j]; ts2 += red1[j]; }
    float mean = ts * (1.f / E_DIM);
    float var  = ts2 * (1.f / E_DIM) - mean * mean;
    float rstd = rsqrtf(var + 1e-5f);
    __half* orow = out + (size_t)t * E_DIM;
#pragma unroll
    for (int j = 0; j < 5; j++) {
        int idx = threadIdx.x + j * 256;
        orow[idx] = __float2half_rn((vals[j] - mean) * rstd * w[idx] + b[idx]);
    }
}

// ---------------- RoPE table: cos/sin per (token, freq) ------------
__global__ void __launch_bounds__(256) rope_table_kernel(
    const int* __restrict__ cu, int nb)
{
    int t = blockIdx.x * 8 + (threadIdx.x >> 5);
    int f = threadIdx.x & 31;
    int seg = 0;
    for (int bb = 1; bb < nb; bb++) if (t >= cu[bb]) seg = bb;
    float pos = (float)(t - cu[seg]);
    const float kfreq = -0.2878231366f; // -ln(10000)/32
    float ang = pos * __expf((float)f * kfreq);
    float sn, c;
    sincosf(ang, &sn, &c);
    g_cos[t * 32 + f] = c;
    g_sin[t * 32 + f] = sn;
}

// ------------- LayerNorm (no bias) + RoPE, in place (tf32-rounded) -
__global__ void __launch_bounds__(256) lnrope_kernel(
    float* __restrict__ q, float* __restrict__ k,
    const float* __restrict__ wq, const float* __restrict__ wk)
{
    int t = blockIdx.x;
    int part = blockIdx.y;
    __shared__ float sb[E_DIM];
    __shared__ float red0[8], red1[8];
    __shared__ float s_stats[2];
    int lane = threadIdx.x & 31, wid = threadIdx.x >> 5;

    float* base = (part ? k : q) + (size_t)t * E_DIM;
    const float* w = part ? wk : wq;
    float s = 0.f, s2 = 0.f;
    for (int i = threadIdx.x; i < E_DIM; i += 256) {
        float v = base[i];
        sb[i] = v; s += v; s2 += v * v;
    }
#pragma unroll
    for (int o = 16; o; o >>= 1) {
        s  += __shfl_xor_sync(0xffffffffu, s,  o);
        s2 += __shfl_xor_sync(0xffffffffu, s2, o);
    }
    if (lane == 0) { red0[wid] = s; red1[wid] = s2; }
    __syncthreads();
    if (threadIdx.x == 0) {
        float ts = 0.f, ts2 = 0.f;
#pragma unroll
        for (int j = 0; j < 8; j++) { ts += red0[j]; ts2 += red1[j]; }
        float mean = ts * (1.f / E_DIM);
        float var  = ts2 * (1.f / E_DIM) - mean * mean;
        s_stats[0] = mean;
        s_stats[1] = rsqrtf(var + 1e-5f);
    }
    __syncthreads();
    float mean = s_stats[0], rstd = s_stats[1];
    for (int i = threadIdx.x; i < E_DIM; i += 256) {
        int ld = i & 63;
        float xn = (sb[i] - mean) * rstd * w[i];
        int pi = (ld < 32) ? (i + 32) : (i - 32);
        float pn = (sb[pi] - mean) * rstd * w[pi];
        int fi = ld & 31;
        float c  = g_cos[t * 32 + fi];
        float sn = g_sin[t * 32 + fi];
        float rot = (ld < 32) ? -pn : pn;
        base[i] = f2tff(xn * c + rot * sn);
    }
}

// ------------- fp16 GEMM core, 3-stage cp.async pipeline -----------
// BM=BN=128, BK=16. 128 threads (4 warps 2x2, warp tile 64x64), fp32
// accumulate. Smem row stride 24 halfs (48B): fragment banks
// (gid*12+tig) mod 32 = full permutation, conflict-free. 3 stages x
// 12KB = 36.9KB -> regs (launch_bounds 128,3) are the occupancy limit.
#define HROW_B 48                             // bytes per smem row
#define HTILE_B (128 * HROW_B)                // 6144
#define HSTAGE_B (2 * HTILE_B)                // A then B: 12288
#define GEMM_SMEM_BYTES (3 * HSTAGE_B)        // 36864

__device__ __forceinline__ void gemm_body(
    const __half* __restrict__ A, const __half* __restrict__ B,
    float* __restrict__ C, int bm, int bn, int N, int K, bool rnd)
{
    extern __shared__ char dynsm[];
    unsigned sb_u = (unsigned)__cvta_generic_to_shared(dynsm);

    int tid = threadIdx.x, lane = tid & 31, warp = tid >> 5;
    int gid = lane >> 2, tig = lane & 3;
    int wm = (warp >> 1) * 64, wn = (warp & 1) * 64;

    float acc[4][8][4];
#pragma unroll
    for (int i = 0; i < 4; i++)
#pragma unroll
        for (int j = 0; j < 8; j++)
#pragma unroll
            for (int l = 0; l < 4; l++) acc[i][j][l] = 0.f;

    int lr = tid >> 1;           // 0..63
    int hc = tid & 1;            // 16B chunk within row (8 halfs)
    const __half* Ap = A + (size_t)(bm + lr) * K + hc * 8;
    const __half* Bp = B + (size_t)(bn + lr) * K + hc * 8;

#define ISSUE(S, K0) { \
    int s_ = (S); int k0_ = (K0); \
    unsigned as_ = sb_u + (unsigned)s_ * HSTAGE_B; \
    unsigned bs_ = as_ + HTILE_B; \
    _Pragma("unroll") \
    for (int ii = 0; ii < 2; ii++) { \
        unsigned ro_ = (unsigned)(lr + ii * 64) * HROW_B + (unsigned)hc * 16; \
        cpa16u(as_ + ro_, Ap + (size_t)ii * 64 * K + k0_); \
        cpa16u(bs_ + ro_, Bp + (size_t)ii * 64 * K + k0_); \
    } }

#define COMPUTE(S) { \
    const unsigned* Au = (const unsigned*)(dynsm + (S) * HSTAGE_B); \
    const unsigned* Bu = Au + HTILE_B / 4; \
    unsigned af[4][4]; \
    _Pragma("unroll") \
    for (int mf = 0; mf < 4; mf++) { \
        int base = (wm + mf * 16 + gid) * 12 + tig; \
        af[mf][0] = Au[base]; \
        af[mf][1] = Au[base + 96]; \
        af[mf][2] = Au[base + 4]; \
        af[mf][3] = Au[base + 100]; \
    } \
    _Pragma("unroll") \
    for (int nf = 0; nf < 8; nf++) { \
        int bidx = (wn + nf * 8 + gid) * 12 + tig; \
        unsigned b0 = Bu[bidx]; \
        unsigned b1 = Bu[bidx + 4]; \
        mma_f16(acc[0][nf], af[0], b0, b1); \
        mma_f16(acc[1][nf], af[1], b0, b1); \
        mma_f16(acc[2][nf], af[2], b0, b1); \
        mma_f16(acc[3][nf], af[3], b0, b1); \
    } }

    int NT = K / 16;   // 80
    ISSUE(0, 0);  CP_COMMIT();
    ISSUE(1, 16); CP_COMMIT();
    int cs = 0;        // compute stage = i % 3
    for (int i = 0; i < NT; i++) {
        CP_WAIT(1);
        __syncthreads();
        COMPUTE(cs);
        // stage (i+2)%3 == (i-1)%3 was last read in compute(i-1);
        // the barrier above guarantees all warps finished it.
        if (i + 2 < NT) {
            int ns = cs - 1; if (ns < 0) ns = 2;   // (i+2)%3
            ISSUE(ns, (i + 2) * 16);
        }
        CP_COMMIT();   // empty groups at tail keep the wait count uniform
        cs = (cs == 2) ? 0 : cs + 1;
    }

#pragma unroll
    for (int mf = 0; mf < 4; mf++)
#pragma unroll
        for (int nf = 0; nf < 8; nf++) {
            int row = bm + wm + mf * 16 + gid;
            int col = bn + wn + nf * 8 + 2 * tig;
            float v0 = acc[mf][nf][0], v1 = acc[mf][nf][1];
            float v2 = acc[mf][nf][2], v3 = acc[mf][nf][3];
            if (rnd) { v0 = f2tff(v0); v1 = f2tff(v1); v2 = f2tff(v2); v3 = f2tff(v3); }
            *(float2*)&C[(size_t)row * N + col] = make_float2(v0, v1);
            *(float2*)&C[(size_t)(row + 8) * N + col] = make_float2(v2, v3);
        }
#undef ISSUE
#undef COMPUTE
}

// Merged QKV projection: grid (30, 64); v output tf32-rounded.
__global__ void __launch_bounds__(128, 3) gemm_qkv(
    float* __restrict__ q, float* __restrict__ k, float* __restrict__ v)
{
    int which = blockIdx.x / 10;
    int bn = (blockIdx.x % 10) * 128;
    int bm = blockIdx.y * 128;
    const __half* B = (which == 0) ? g_wqh : (which == 1) ? g_wkh : g_wvh;
    float* C = (which == 0) ? q : (which == 1) ? k : v;
    gemm_body(g_hh, B, C, bm, bn, E_DIM, E_DIM, which == 2);
}

// Single GEMM (output projection): A = g_oh, B = g_woh
__global__ void __launch_bounds__(128, 3) gemm_one(float* __restrict__ C)
{
    gemm_body(g_oh, g_woh, C, blockIdx.y * 128, blockIdx.x * 128,
              E_DIM, E_DIM, false);
}

// ------------- flash attention (R12 passing version; fp16 o out) ---
#define KS_STRIDE 68
#define VS_STRIDE 72
#define PS_STRIDE 68
#define ATT_STAGE_F (64 * KS_STRIDE + 64 * VS_STRIDE)   // 8960 floats
#define ATT_P_F (128 * PS_STRIDE)                        // 8704 floats
#define ATT_SMEM_BYTES ((2 * ATT_STAGE_F + ATT_P_F) * 4) // 106496

__global__ void __launch_bounds__(128) attn_tf32(
    const float* __restrict__ q, const float* __restrict__ k,
    const float* __restrict__ v, __half* __restrict__ o)
{
    extern __shared__ float sm[];
    float* PS = sm + 2 * ATT_STAGE_F;

    int b = blockIdx.z, h = blockIdx.y, qt = blockIdx.x;
    int tid = threadIdx.x;
    int warp = tid >> 5, lane = tid & 31;
    int gid = lane >> 2, tig = lane & 3;
    int m0 = warp * 32;
    int tq0 = b * SEQ + qt * 128;

#define ATT_ISSUE(KT, S) { \
    int kt_ = (KT); int s_ = (S); \
    float* Ks_ = sm + s_ * ATT_STAGE_F; \
    float* Vs_ = Ks_ + 64 * KS_STRIDE; \
    int tk0_ = b * SEQ + kt_ * 64; \
    _Pragma("unroll") \
    for (int ii = 0; ii < 8; ii++) { \
        int idx_ = tid + ii * 128; \
        int r_ = idx_ >> 4, c4_ = (idx_ & 15) << 2; \
        const size_t goff_ = (size_t)(tk0_ + r_) * E_DIM + h * 64 + c4_; \
        cpa16(&Ks_[r_ * KS_STRIDE + c4_], &k[goff_]); \
        cpa16(&Vs_[r_ * VS_STRIDE + c4_], &v[goff_]); \
    } }

    ATT_ISSUE(0, 0); CP_COMMIT();

    unsigned qf[8][2][4];
#pragma unroll
    for (int mf = 0; mf < 2; mf++) {
        const float* qp = q + (size_t)(tq0 + m0 + mf * 16 + gid) * E_DIM + h * 64;
#pragma unroll
        for (int ks = 0; ks < 8; ks++) {
            int c = ks * 8 + tig;
            qf[ks][mf][0] = f2tf(qp[c] * 0.125f);
            qf[ks][mf][1] = f2tf(qp[(size_t)8 * E_DIM + c] * 0.125f);
            qf[ks][mf][2] = f2tf(qp[c + 4] * 0.125f);
            qf[ks][mf][3] = f2tf(qp[(size_t)8 * E_DIM + c + 4] * 0.125f);
        }
    }

    float mrow[2][2], lrow[2][2];
#pragma unroll
    for (int mf = 0; mf < 2; mf++) {
        mrow[mf][0] = -1e30f; mrow[mf][1] = -1e30f;
        lrow[mf][0] = 0.f;    lrow[mf][1] = 0.f;
    }
    float oc[2][8][4];
#pragma unroll
    for (int mf = 0; mf < 2; mf++)
#pragma unroll
        for (int j = 0; j < 8; j++)
#pragma unroll
            for (int l = 0; l < 4; l++) oc[mf][j][l] = 0.f;

    for (int kt = 0; kt < SEQ / 64; kt++) {
        int cur = kt & 1;
        float* Ks = sm + cur * ATT_STAGE_F;
        float* Vs = Ks + 64 * KS_STRIDE;

        CP_WAIT(0);
        __syncthreads();

        float sc[2][8][4];
#pragma unroll
        for (int mf = 0; mf < 2; mf++)
#pragma unroll
            for (int j = 0; j < 8; j++)
#pragma unroll
                for (int l = 0; l < 4; l++) sc[mf][j][l] = 0.f;
#pragma unroll
        for (int ks = 0; ks < 8; ks++) {
#pragma unroll
            for (int nf = 0; nf < 8; nf++) {
                int bb = (nf * 8 + gid) * KS_STRIDE + ks * 8 + tig;
                unsigned b0 = __float_as_uint(Ks[bb]);
                unsigned b1 = __float_as_uint(Ks[bb + 4]);
                mma_tf32(sc[0][nf], qf[ks][0], b0, b1);
                mma_tf32(sc[1][nf], qf[ks][1], b0, b1);
            }
        }

#pragma unroll
        for (int mf = 0; mf < 2; mf++) {
            float tm0 = -1e30f, tm1 = -1e30f;
#pragma unroll
            for (int nf = 0; nf < 8; nf++) {
                tm0 = fmaxf(tm0, fmaxf(sc[mf][nf][0], sc[mf][nf][1]));
                tm1 = fmaxf(tm1, fmaxf(sc[mf][nf][2], sc[mf][nf][3]));
            }
            tm0 = fmaxf(tm0, __shfl_xor_sync(0xffffffffu, tm0, 1));
            tm0 = fmaxf(tm0, __shfl_xor_sync(0xffffffffu, tm0, 2));
            tm1 = fmaxf(tm1, __shfl_xor_sync(0xffffffffu, tm1, 1));
            tm1 = fmaxf(tm1, __shfl_xor_sync(0xffffffffu, tm1, 2));
            float mn0 = fmaxf(mrow[mf][0], tm0), mn1 = fmaxf(mrow[mf][1], tm1);
            float cor0 = __expf(mrow[mf][0] - mn0);
            float cor1 = __expf(mrow[mf][1] - mn1);
            float ls0 = 0.f, ls1 = 0.f;
#pragma unroll
            for (int nf = 0; nf < 8; nf++) {
                float p0 = __expf(sc[mf][nf][0] - mn0);
                float p1 = __expf(sc[mf][nf][1] - mn0);
                float p2 = __expf(sc[mf][nf][2] - mn1);
                float p3 = __expf(sc[mf][nf][3] - mn1);
                ls0 += p0 + p1; ls1 += p2 + p3;
                int pb = (m0 + mf * 16 + gid) * PS_STRIDE + nf * 8 + 2 * tig;
                *(float2*)&PS[pb] = make_float2(f2tff(p0), f2tff(p1));
                *(float2*)&PS[pb + 8 * PS_STRIDE] = make_float2(f2tff(p2), f2tff(p3));
            }
            ls0 += __shfl_xor_sync(0xffffffffu, ls0, 1);
            ls0 += __shfl_xor_sync(0xffffffffu, ls0, 2);
            ls1 += __shfl_xor_sync(0xffffffffu, ls1, 1);
            ls1 += __shfl_xor_sync(0xffffffffu, ls1, 2);
            lrow[mf][0] = lrow[mf][0] * cor0 + ls0;
            lrow[mf][1] = lrow[mf][1] * cor1 + ls1;
            mrow[mf][0] = mn0; mrow[mf][1] = mn1;
#pragma unroll
            for (int nf = 0; nf < 8; nf++) {
                oc[mf][nf][0] *= cor0; oc[mf][nf][1] *= cor0;
                oc[mf][nf][2] *= cor1; oc[mf][nf][3] *= cor1;
            }
        }
        __syncwarp();

#pragma unroll
        for (int ks = 0; ks < 8; ks++) {
            unsigned af[2][4];
#pragma unroll
            for (int mf = 0; mf < 2; mf++) {
                int ab = (m0 + mf * 16 + gid) * PS_STRIDE + ks * 8 + tig;
                af[mf][0] = __float_as_uint(PS[ab]);
                af[mf][1] = __float_as_uint(PS[ab + 8 * PS_STRIDE]);
                af[mf][2] = __float_as_uint(PS[ab + 4]);
                af[mf][3] = __float_as_uint(PS[ab + 8 * PS_STRIDE + 4]);
            }
#pragma unroll
            for (int nf = 0; nf < 8; nf++) {
                int vb = (ks * 8 + tig) * VS_STRIDE + nf * 8 + gid;
                unsigned b0 = __float_as_uint(Vs[vb]);
                unsigned b1 = __float_as_uint(Vs[vb + 4 * VS_STRIDE]);
                mma_tf32(oc[0][nf], af[0], b0, b1);
                mma_tf32(oc[1][nf], af[1], b0, b1);
            }
        }

        if (kt + 1 < SEQ / 64) { ATT_ISSUE(kt + 1, 1 - cur); }
        CP_COMMIT();
    }

    // o written fp16 -> Wout GEMM consumes it directly
#pragma unroll
    for (int mf = 0; mf < 2; mf++) {
        float il0 = 1.f / lrow[mf][0], il1 = 1.f / lrow[mf][1];
        int row = tq0 + m0 + mf * 16 + gid;
#pragma unroll
        for (int nf = 0; nf < 8; nf++) {
            int col = h * 64 + nf * 8 + 2 * tig;
            *(__half2*)&o[(size_t)row * E_DIM + col] =
                __floats2half2_rn(oc[mf][nf][0] * il0, oc[mf][nf][1] * il0);
            *(__half2*)&o[(size_t)(row + 8) * E_DIM + col] =
                __floats2half2_rn(oc[mf][nf][2] * il1, oc[mf][nf][3] * il1);
        }
    }
#undef ATT_ISSUE
}

// -------------------------------------------------------------------
extern "C" void kernel_launch(void* const* d_in, const int* in_sizes, int n_in,
                              void* d_out, int out_size)
{
    const float* x  = (const float*)d_in[0];
    const int*   cu = (const int*)d_in[1];
    int idx = 2;
    if (in_sizes[2] == 1) idx = 3;  // skip scalar max_len if present
    const float* norm_w = (const float*)d_in[idx++];
    const float* norm_b = (const float*)d_in[idx++];
    const float* Wq     = (const float*)d_in[idx++];
    const float* Wk     = (const float*)d_in[idx++];
    const float* Wv     = (const float*)d_in[idx++];
    const float* Wout   = (const float*)d_in[idx++];
    const float* lnq_w  = (const float*)d_in[idx++];
    const float* lnk_w  = (const float*)d_in[idx++];
    float* out = (float*)d_out;

    int nb = in_sizes[1] - 1;

    __half *hh, *oh;
    float *q, *k, *v;
    cudaGetSymbolAddress((void**)&hh, g_hh);
    cudaGetSymbolAddress((void**)&q, g_q);
    cudaGetSymbolAddress((void**)&k, g_k);
    cudaGetSymbolAddress((void**)&v, g_v);
    cudaGetSymbolAddress((void**)&oh, g_oh);

    cudaFuncSetAttribute(gemm_qkv, cudaFuncAttributeMaxDynamicSharedMemorySize,
                         GEMM_SMEM_BYTES);
    cudaFuncSetAttribute(gemm_one, cudaFuncAttributeMaxDynamicSharedMemorySize,
                         GEMM_SMEM_BYTES);
    cudaFuncSetAttribute(attn_tf32, cudaFuncAttributeMaxDynamicSharedMemorySize,
                         ATT_SMEM_BYTES);

    // 0) round weights to fp16 once per call
    wprep_kernel<<<dim3(E_DIM * E_DIM / 1024, 4), 256>>>(Wq, Wk, Wv, Wout);

    // 1) pre-norm (fp16 output) + rope table
    ln_kernel<<<T_TOK, 256>>>(x, norm_w, norm_b, hh);
    rope_table_kernel<<<T_TOK / 8, 256>>>(cu, nb);

    // 2) merged Q/K/V projections (fp16 MMA, fp32 out)
    gemm_qkv<<<dim3(30, T_TOK / 128), 128, GEMM_SMEM_BYTES>>>(q, k, v);

    // 3) q/k LayerNorm + RoPE (in place, tf32-rounded output)
    lnrope_kernel<<<dim3(T_TOK, 2), 256>>>(q, k, lnq_w, lnk_w);

    // 4) attention (R12 version; fp16 o output)
    dim3 agrid(SEQ / 128, NHEAD, NBATCH);
    attn_tf32<<<agrid, 128, ATT_SMEM_BYTES>>>(q, k, v, oh);

    // 5) output projection (fp16 MMA)
    gemm_one<<<dim3(E_DIM / 128, T_TOK / 128), 128, GEMM_SMEM_BYTES>>>(out);
}

// round 16
// speedup vs baseline: 1.6401x; 1.2647x over previous
#include <cuda_runtime.h>
#include <cuda_fp16.h>
#include <math.h>

#define E_DIM 1280
#define NHEAD 20
#define DHEAD 64
#define T_TOK 8192
#define SEQ   1024
#define NBATCH 8

// ---------------- scratch (no allocations allowed) ----------------
__device__ __half g_hh[T_TOK * E_DIM];     // LN output (fp16)
__device__ float  g_q[T_TOK * E_DIM];      // q (fp32, RoPE'd in place)
__device__ float  g_k[T_TOK * E_DIM];      // k pre-LN (fp32, gemm out)
__device__ __half g_kh[T_TOK * E_DIM];     // k post-LN+RoPE (fp16)
__device__ __half g_vh[T_TOK * E_DIM];     // v (fp16, gemm out)
__device__ __half g_oh[T_TOK * E_DIM];     // attention output (fp16)
__device__ __half g_wqh[E_DIM * E_DIM];
__device__ __half g_wkh[E_DIM * E_DIM];
__device__ __half g_wvh[E_DIM * E_DIM];
__device__ __half g_woh[E_DIM * E_DIM];
__device__ float  g_cos[T_TOK * 32];
__device__ float  g_sin[T_TOK * 32];

// ---------------- helpers ----------------
__device__ __forceinline__ unsigned h2u(float a, float b) {
    __half2 t = __floats2half2_rn(a, b);
    return *(unsigned*)&t;
}

__device__ __forceinline__ void mma_f16(float c[4], const unsigned a[4],
                                        unsigned b0, unsigned b1) {
    asm volatile(
        "mma.sync.aligned.m16n8k16.row.col.f32.f16.f16.f32 "
        "{%0,%1,%2,%3}, {%4,%5,%6,%7}, {%8,%9}, {%0,%1,%2,%3};\n"
        : "+f"(c[0]), "+f"(c[1]), "+f"(c[2]), "+f"(c[3])
        : "r"(a[0]), "r"(a[1]), "r"(a[2]), "r"(a[3]), "r"(b0), "r"(b1));
}

__device__ __forceinline__ void ldsm_x2_t(unsigned& r0, unsigned& r1,
                                          unsigned addr) {
    asm volatile("ldmatrix.sync.aligned.m8n8.x2.trans.shared.b16 {%0,%1}, [%2];"
                 : "=r"(r0), "=r"(r1) : "r"(addr));
}

__device__ __forceinline__ void cpa16(void* s, const void* g) {
    unsigned saddr = (unsigned)__cvta_generic_to_shared(s);
    asm volatile("cp.async.ca.shared.global [%0], [%1], 16;\n"
                 :: "r"(saddr), "l"(g));
}
__device__ __forceinline__ void cpa16u(unsigned saddr, const void* g) {
    asm volatile("cp.async.ca.shared.global [%0], [%1], 16;\n"
                 :: "r"(saddr), "l"(g));
}
#define CP_COMMIT() asm volatile("cp.async.commit_group;\n" ::: "memory")
#define CP_WAIT(N)  asm volatile("cp.async.wait_group " #N ";\n" ::: "memory")

// ------------- weight prep: round to fp16 in global ---------------
__global__ void __launch_bounds__(256) wprep_kernel(
    const float* __restrict__ Wq, const float* __restrict__ Wk,
    const float* __restrict__ Wv, const float* __restrict__ Wo)
{
    const float* src = (blockIdx.y == 0) ? Wq : (blockIdx.y == 1) ? Wk :
                       (blockIdx.y == 2) ? Wv : Wo;
    __half* dst = (blockIdx.y == 0) ? g_wqh : (blockIdx.y == 1) ? g_wkh :
                  (blockIdx.y == 2) ? g_wvh : g_woh;
    int i = (blockIdx.x * 256 + threadIdx.x) * 4;
    float4 v = *(const float4*)&src[i];
    *(__half2*)&dst[i]     = __floats2half2_rn(v.x, v.y);
    *(__half2*)&dst[i + 2] = __floats2half2_rn(v.z, v.w);
}

// ---------------- LayerNorm (with bias) : x -> h (fp16) ------------
__global__ void __launch_bounds__(256) ln_kernel(
    const float* __restrict__ x, const float* __restrict__ w,
    const float* __restrict__ b, __half* __restrict__ out)
{
    int t = blockIdx.x;
    const float* xr = x + (size_t)t * E_DIM;
    float vals[5];
    float s = 0.f, s2 = 0.f;
#pragma unroll
    for (int j = 0; j < 5; j++) {
        float v = xr[threadIdx.x + j * 256];
        vals[j] = v; s += v; s2 += v * v;
    }
    __shared__ float red0[8], red1[8];
    int lane = threadIdx.x & 31, wid = threadIdx.x >> 5;
#pragma unroll
    for (int o = 16; o; o >>= 1) {
        s  += __shfl_xor_sync(0xffffffffu, s,  o);
        s2 += __shfl_xor_sync(0xffffffffu, s2, o);
    }
    if (lane == 0) { red0[wid] = s; red1[wid] = s2; }
    __syncthreads();
    float ts = 0.f, ts2 = 0.f;
#pragma unroll
    for (int j = 0; j < 8; j++) { ts += red0[j]; ts2 += red1[j]; }
    float mean = ts * (1.f / E_DIM);
    float var  = ts2 * (1.f / E_DIM) - mean * mean;
    float rstd = rsqrtf(var + 1e-5f);
    __half* orow = out + (size_t)t * E_DIM;
#pragma unroll
    for (int j = 0; j < 5; j++) {
        int idx = threadIdx.x + j * 256;
        orow[idx] = __float2half_rn((vals[j] - mean) * rstd * w[idx] + b[idx]);
    }
}

// ---------------- RoPE table: cos/sin per (token, freq) ------------
__global__ void __launch_bounds__(256) rope_table_kernel(
    const int* __restrict__ cu, int nb)
{
    int t = blockIdx.x * 8 + (threadIdx.x >> 5);
    int f = threadIdx.x & 31;
    int seg = 0;
    for (int bb = 1; bb < nb; bb++) if (t >= cu[bb]) seg = bb;
    float pos = (float)(t - cu[seg]);
    const float kfreq = -0.2878231366f; // -ln(10000)/32
    float ang = pos * __expf((float)f * kfreq);
    float sn, c;
    sincosf(ang, &sn, &c);
    g_cos[t * 32 + f] = c;
    g_sin[t * 32 + f] = sn;
}

// ------------- LayerNorm (no bias) + RoPE --------------------------
// part 0: q in-place fp32. part 1: k fp32 -> g_kh fp16.
__global__ void __launch_bounds__(256) lnrope_kernel(
    float* __restrict__ q, const float* __restrict__ k,
    __half* __restrict__ kh,
    const float* __restrict__ wq, const float* __restrict__ wk)
{
    int t = blockIdx.x;
    int part = blockIdx.y;
    __shared__ float sb[E_DIM];
    __shared__ float red0[8], red1[8];
    __shared__ float s_stats[2];
    int lane = threadIdx.x & 31, wid = threadIdx.x >> 5;

    const float* src = (part ? k : q) + (size_t)t * E_DIM;
    const float* w = part ? wk : wq;
    float s = 0.f, s2 = 0.f;
    for (int i = threadIdx.x; i < E_DIM; i += 256) {
        float v = src[i];
        sb[i] = v; s += v; s2 += v * v;
    }
#pragma unroll
    for (int o = 16; o; o >>= 1) {
        s  += __shfl_xor_sync(0xffffffffu, s,  o);
        s2 += __shfl_xor_sync(0xffffffffu, s2, o);
    }
    if (lane == 0) { red0[wid] = s; red1[wid] = s2; }
    __syncthreads();
    if (threadIdx.x == 0) {
        float ts = 0.f, ts2 = 0.f;
#pragma unroll
        for (int j = 0; j < 8; j++) { ts += red0[j]; ts2 += red1[j]; }
        float mean = ts * (1.f / E_DIM);
        float var  = ts2 * (1.f / E_DIM) - mean * mean;
        s_stats[0] = mean;
        s_stats[1] = rsqrtf(var + 1e-5f);
    }
    __syncthreads();
    float mean = s_stats[0], rstd = s_stats[1];
    for (int i = threadIdx.x; i < E_DIM; i += 256) {
        int ld = i & 63;
        float xn = (sb[i] - mean) * rstd * w[i];
        int pi = (ld < 32) ? (i + 32) : (i - 32);
        float pn = (sb[pi] - mean) * rstd * w[pi];
        int fi = ld & 31;
        float c  = g_cos[t * 32 + fi];
        float sn = g_sin[t * 32 + fi];
        float rot = (ld < 32) ? -pn : pn;
        float val = xn * c + rot * sn;
        if (part) kh[(size_t)t * E_DIM + i] = __float2half_rn(val);
        else      q[(size_t)t * E_DIM + i] = val;
    }
}

// ------------- fp16 GEMM core, 3-stage cp.async pipeline -----------
// BM=BN=128, BK=16, 128 threads (4 warps 2x2, 64x64 warp tiles),
// fp32 accumulate. Row stride 24 halfs: conflict-free fragments.
#define HROW_B 48
#define HTILE_B (128 * HROW_B)                // 6144
#define HSTAGE_B (2 * HTILE_B)                // 12288
#define GEMM_SMEM_BYTES (3 * HSTAGE_B)        // 36864

__device__ __forceinline__ void gemm_body(
    const __half* __restrict__ A, const __half* __restrict__ B,
    float* __restrict__ Cf, __half* __restrict__ Ch,
    int bm, int bn, int N, int K)
{
    extern __shared__ char dynsm[];
    unsigned sb_u = (unsigned)__cvta_generic_to_shared(dynsm);

    int tid = threadIdx.x, lane = tid & 31, warp = tid >> 5;
    int gid = lane >> 2, tig = lane & 3;
    int wm = (warp >> 1) * 64, wn = (warp & 1) * 64;

    float acc[4][8][4];
#pragma unroll
    for (int i = 0; i < 4; i++)
#pragma unroll
        for (int j = 0; j < 8; j++)
#pragma unroll
            for (int l = 0; l < 4; l++) acc[i][j][l] = 0.f;

    int lr = tid >> 1;           // 0..63
    int hc = tid & 1;
    const __half* Ap = A + (size_t)(bm + lr) * K + hc * 8;
    const __half* Bp = B + (size_t)(bn + lr) * K + hc * 8;

#define ISSUE(S, K0) { \
    int s_ = (S); int k0_ = (K0); \
    unsigned as_ = sb_u + (unsigned)s_ * HSTAGE_B; \
    unsigned bs_ = as_ + HTILE_B; \
    _Pragma("unroll") \
    for (int ii = 0; ii < 2; ii++) { \
        unsigned ro_ = (unsigned)(lr + ii * 64) * HROW_B + (unsigned)hc * 16; \
        cpa16u(as_ + ro_, Ap + (size_t)ii * 64 * K + k0_); \
        cpa16u(bs_ + ro_, Bp + (size_t)ii * 64 * K + k0_); \
    } }

#define COMPUTE(S) { \
    const unsigned* Au = (const unsigned*)(dynsm + (S) * HSTAGE_B); \
    const unsigned* Bu = Au + HTILE_B / 4; \
    unsigned af[4][4]; \
    _Pragma("unroll") \
    for (int mf = 0; mf < 4; mf++) { \
        int base = (wm + mf * 16 + gid) * 12 + tig; \
        af[mf][0] = Au[base]; \
        af[mf][1] = Au[base + 96]; \
        af[mf][2] = Au[base + 4]; \
        af[mf][3] = Au[base + 100]; \
    } \
    _Pragma("unroll") \
    for (int nf = 0; nf < 8; nf++) { \
        int bidx = (wn + nf * 8 + gid) * 12 + tig; \
        unsigned b0 = Bu[bidx]; \
        unsigned b1 = Bu[bidx + 4]; \
        mma_f16(acc[0][nf], af[0], b0, b1); \
        mma_f16(acc[1][nf], af[1], b0, b1); \
        mma_f16(acc[2][nf], af[2], b0, b1); \
        mma_f16(acc[3][nf], af[3], b0, b1); \
    } }

    int NT = K / 16;   // 80
    ISSUE(0, 0);  CP_COMMIT();
    ISSUE(1, 16); CP_COMMIT();
    int cs = 0;
    for (int i = 0; i < NT; i++) {
        CP_WAIT(1);
        __syncthreads();
        COMPUTE(cs);
        if (i + 2 < NT) {
            int ns = cs - 1; if (ns < 0) ns = 2;
            ISSUE(ns, (i + 2) * 16);
        }
        CP_COMMIT();
        cs = (cs == 2) ? 0 : cs + 1;
    }

#pragma unroll
    for (int mf = 0; mf < 4; mf++)
#pragma unroll
        for (int nf = 0; nf < 8; nf++) {
            int row = bm + wm + mf * 16 + gid;
            int col = bn + wn + nf * 8 + 2 * tig;
            if (Ch) {
                *(__half2*)&Ch[(size_t)row * N + col] =
                    __floats2half2_rn(acc[mf][nf][0], acc[mf][nf][1]);
                *(__half2*)&Ch[(size_t)(row + 8) * N + col] =
                    __floats2half2_rn(acc[mf][nf][2], acc[mf][nf][3]);
            } else {
                *(float2*)&Cf[(size_t)row * N + col] =
                    make_float2(acc[mf][nf][0], acc[mf][nf][1]);
                *(float2*)&Cf[(size_t)(row + 8) * N + col] =
                    make_float2(acc[mf][nf][2], acc[mf][nf][3]);
            }
        }
#undef ISSUE
#undef COMPUTE
}

// Merged QKV: q,k fp32 out; v fp16 out (no LN/RoPE needed for v).
__global__ void __launch_bounds__(128, 3) gemm_qkv(
    float* __restrict__ q, float* __restrict__ k)
{
    int which = blockIdx.x / 10;
    int bn = (blockIdx.x % 10) * 128;
    int bm = blockIdx.y * 128;
    const __half* B = (which == 0) ? g_wqh : (which == 1) ? g_wkh : g_wvh;
    float* Cf = (which == 0) ? q : (which == 1) ? k : (float*)0;
    __half* Ch = (which == 2) ? g_vh : (__half*)0;
    gemm_body(g_hh, B, Cf, Ch, bm, bn, E_DIM, E_DIM);
}

// Output projection: A = g_oh, B = g_woh, fp32 out.
__global__ void __launch_bounds__(128, 3) gemm_one(float* __restrict__ C)
{
    gemm_body(g_oh, g_woh, C, (__half*)0,
              blockIdx.y * 128, blockIdx.x * 128, E_DIM, E_DIM);
}

// ------------- flash attention, fp16 MMA, register-resident P ------
// 128 q-rows/CTA, 4 warps x 32 rows. m16n8k16: P's A-fragment cols
// {2tig,2tig+1} == the QK accumulator cols each thread holds -> P
// converts to half2 fragments in registers (no smem, no shuffles).
// K B-frags: direct half2 LDS (stride 72 -> conflict-free).
// V B-frags: ldmatrix.x2.trans.
#define KH_STRIDE 72
#define ATT_STAGE_H (2 * 64 * KH_STRIDE)        // K then V: 9216 halfs
#define ATT_SMEM_BYTES (2 * ATT_STAGE_H * 2)    // 36864 bytes

__global__ void __launch_bounds__(128) attn_f16(
    const float* __restrict__ q, const __half* __restrict__ kh,
    const __half* __restrict__ vh, __half* __restrict__ o)
{
    extern __shared__ __half smh[];

    int b = blockIdx.z, h = blockIdx.y, qt = blockIdx.x;
    int tid = threadIdx.x;
    int warp = tid >> 5, lane = tid & 31;
    int gid = lane >> 2, tig = lane & 3;
    int m0 = warp * 32;
    int tq0 = b * SEQ + qt * 128;

#define ATT_ISSUE(KT, S) { \
    int kt_ = (KT); \
    __half* Ks_ = smh + (S) * ATT_STAGE_H; \
    __half* Vs_ = Ks_ + 64 * KH_STRIDE; \
    int tk0_ = b * SEQ + kt_ * 64; \
    _Pragma("unroll") \
    for (int ii = 0; ii < 4; ii++) { \
        int idx_ = tid + ii * 128; \
        int r_ = idx_ >> 3, c8_ = (idx_ & 7) << 3; \
        const size_t goff_ = (size_t)(tk0_ + r_) * E_DIM + h * 64 + c8_; \
        cpa16(&Ks_[r_ * KH_STRIDE + c8_], &kh[goff_]); \
        cpa16(&Vs_[r_ * KH_STRIDE + c8_], &vh[goff_]); \
    } }

    ATT_ISSUE(0, 0); CP_COMMIT();

    // Q fragments (fp32 -> fp16, pre-scaled by 0.125)
    unsigned qf[4][2][4];
#pragma unroll
    for (int mf = 0; mf < 2; mf++) {
        const float* qp = q + (size_t)(tq0 + m0 + mf * 16 + gid) * E_DIM + h * 64;
#pragma unroll
        for (int ks = 0; ks < 4; ks++) {
            int c = ks * 16 + 2 * tig;
            qf[ks][mf][0] = h2u(qp[c] * 0.125f, qp[c + 1] * 0.125f);
            qf[ks][mf][1] = h2u(qp[(size_t)8 * E_DIM + c] * 0.125f,
                                qp[(size_t)8 * E_DIM + c + 1] * 0.125f);
            qf[ks][mf][2] = h2u(qp[c + 8] * 0.125f, qp[c + 9] * 0.125f);
            qf[ks][mf][3] = h2u(qp[(size_t)8 * E_DIM + c + 8] * 0.125f,
                                qp[(size_t)8 * E_DIM + c + 9] * 0.125f);
        }
    }

    float mrow[2][2], lrow[2][2];
#pragma unroll
    for (int mf = 0; mf < 2; mf++) {
        mrow[mf][0] = -1e30f; mrow[mf][1] = -1e30f;
        lrow[mf][0] = 0.f;    lrow[mf][1] = 0.f;
    }
    float oc[2][8][4];
#pragma unroll
    for (int mf = 0; mf < 2; mf++)
#pragma unroll
        for (int j = 0; j < 8; j++)
#pragma unroll
            for (int l = 0; l < 4; l++) oc[mf][j][l] = 0.f;

    for (int kt = 0; kt < SEQ / 64; kt++) {
        int cur = kt & 1;
        __half* Ks = smh + cur * ATT_STAGE_H;
        __half* Vs = Ks + 64 * KH_STRIDE;

        CP_WAIT(0);
        __syncthreads();

        // ---- QK^T: S[32 x 64] per warp, fp16 MMA ----
        float sc[2][8][4];
#pragma unroll
        for (int mf = 0; mf < 2; mf++)
#pragma unroll
            for (int j = 0; j < 8; j++)
#pragma unroll
                for (int l = 0; l < 4; l++) sc[mf][j][l] = 0.f;
#pragma unroll
        for (int ks = 0; ks < 4; ks++) {
#pragma unroll
            for (int nf = 0; nf < 8; nf++) {
                const __half* kr = &Ks[(nf * 8 + gid) * KH_STRIDE + ks * 16 + 2 * tig];
                unsigned b0 = *(const unsigned*)kr;
                unsigned b1 = *(const unsigned*)(kr + 8);
                mma_f16(sc[0][nf], qf[ks][0], b0, b1);
                mma_f16(sc[1][nf], qf[ks][1], b0, b1);
            }
        }

        // ---- online softmax; P -> half2 A-fragments in registers ----
        unsigned pa[2][4][4];
#pragma unroll
        for (int mf = 0; mf < 2; mf++) {
            float tm0 = -1e30f, tm1 = -1e30f;
#pragma unroll
            for (int nf = 0; nf < 8; nf++) {
                tm0 = fmaxf(tm0, fmaxf(sc[mf][nf][0], sc[mf][nf][1]));
                tm1 = fmaxf(tm1, fmaxf(sc[mf][nf][2], sc[mf][nf][3]));
            }
            tm0 = fmaxf(tm0, __shfl_xor_sync(0xffffffffu, tm0, 1));
            tm0 = fmaxf(tm0, __shfl_xor_sync(0xffffffffu, tm0, 2));
            tm1 = fmaxf(tm1, __shfl_xor_sync(0xffffffffu, tm1, 1));
            tm1 = fmaxf(tm1, __shfl_xor_sync(0xffffffffu, tm1, 2));
            float mn0 = fmaxf(mrow[mf][0], tm0), mn1 = fmaxf(mrow[mf][1], tm1);
            float cor0 = __expf(mrow[mf][0] - mn0);
            float cor1 = __expf(mrow[mf][1] - mn1);
            float ls0 = 0.f, ls1 = 0.f;
#pragma unroll
            for (int nf = 0; nf < 8; nf++) {
                float p0 = __expf(sc[mf][nf][0] - mn0);
                float p1 = __expf(sc[mf][nf][1] - mn0);
                float p2 = __expf(sc[mf][nf][2] - mn1);
                float p3 = __expf(sc[mf][nf][3] - mn1);
                ls0 += p0 + p1; ls1 += p2 + p3;
                int ks_ = nf >> 1;
                if ((nf & 1) == 0) {
                    pa[mf][ks_][0] = h2u(p0, p1);   // (row gid,   k=2tig..)
                    pa[mf][ks_][1] = h2u(p2, p3);   // (row gid+8, k=2tig..)
                } else {
                    pa[mf][ks_][2] = h2u(p0, p1);   // (row gid,   k=2tig+8..)
                    pa[mf][ks_][3] = h2u(p2, p3);   // (row gid+8, k=2tig+8..)
                }
            }
            ls0 += __shfl_xor_sync(0xffffffffu, ls0, 1);
            ls0 += __shfl_xor_sync(0xffffffffu, ls0, 2);
            ls1 += __shfl_xor_sync(0xffffffffu, ls1, 1);
            ls1 += __shfl_xor_sync(0xffffffffu, ls1, 2);
            lrow[mf][0] = lrow[mf][0] * cor0 + ls0;
            lrow[mf][1] = lrow[mf][1] * cor1 + ls1;
            mrow[mf][0] = mn0; mrow[mf][1] = mn1;
#pragma unroll
            for (int nf = 0; nf < 8; nf++) {
                oc[mf][nf][0] *= cor0; oc[mf][nf][1] *= cor0;
                oc[mf][nf][2] *= cor1; oc[mf][nf][3] *= cor1;
            }
        }

        // ---- PV: O[32 x 64] += P * V, V fragments via ldmatrix.trans ----
        unsigned vrow = (unsigned)__cvta_generic_to_shared(
                            Vs + (lane & 15) * KH_STRIDE);
#pragma unroll
        for (int ks = 0; ks < 4; ks++) {
#pragma unroll
            for (int nf = 0; nf < 8; nf++) {
                unsigned v0, v1;
                ldsm_x2_t(v0, v1,
                          vrow + (unsigned)(ks * 16 * KH_STRIDE + nf * 8) * 2);
                mma_f16(oc[0][nf], pa[0][ks], v0, v1);
                mma_f16(oc[1][nf], pa[1][ks], v0, v1);
            }
        }

        if (kt + 1 < SEQ / 64) { ATT_ISSUE(kt + 1, 1 - cur); }
        CP_COMMIT();
    }

    // fp16 o output (consumed directly by Wout GEMM)
#pragma unroll
    for (int mf = 0; mf < 2; mf++) {
        float il0 = 1.f / lrow[mf][0], il1 = 1.f / lrow[mf][1];
        int row = tq0 + m0 + mf * 16 + gid;
#pragma unroll
        for (int nf = 0; nf < 8; nf++) {
            int col = h * 64 + nf * 8 + 2 * tig;
            *(__half2*)&o[(size_t)row * E_DIM + col] =
                __floats2half2_rn(oc[mf][nf][0] * il0, oc[mf][nf][1] * il0);
            *(__half2*)&o[(size_t)(row + 8) * E_DIM + col] =
                __floats2half2_rn(oc[mf][nf][2] * il1, oc[mf][nf][3] * il1);
        }
    }
#undef ATT_ISSUE
}

// -------------------------------------------------------------------
extern "C" void kernel_launch(void* const* d_in, const int* in_sizes, int n_in,
                              void* d_out, int out_size)
{
    const float* x  = (const float*)d_in[0];
    const int*   cu = (const int*)d_in[1];
    int idx = 2;
    if (in_sizes[2] == 1) idx = 3;  // skip scalar max_len if present
    const float* norm_w = (const float*)d_in[idx++];
    const float* norm_b = (const float*)d_in[idx++];
    const float* Wq     = (const float*)d_in[idx++];
    const float* Wk     = (const float*)d_in[idx++];
    const float* Wv     = (const float*)d_in[idx++];
    const float* Wout   = (const float*)d_in[idx++];
    const float* lnq_w  = (const float*)d_in[idx++];
    const float* lnk_w  = (const float*)d_in[idx++];
    float* out = (float*)d_out;

    int nb = in_sizes[1] - 1;

    __half *hh, *khp, *vhp, *oh;
    float *q, *k;
    cudaGetSymbolAddress((void**)&hh, g_hh);
    cudaGetSymbolAddress((void**)&q, g_q);
    cudaGetSymbolAddress((void**)&k, g_k);
    cudaGetSymbolAddress((void**)&khp, g_kh);
    cudaGetSymbolAddress((void**)&vhp, g_vh);
    cudaGetSymbolAddress((void**)&oh, g_oh);

    cudaFuncSetAttribute(gemm_qkv, cudaFuncAttributeMaxDynamicSharedMemorySize,
                         GEMM_SMEM_BYTES);
    cudaFuncSetAttribute(gemm_one, cudaFuncAttributeMaxDynamicSharedMemorySize,
                         GEMM_SMEM_BYTES);
    cudaFuncSetAttribute(attn_f16, cudaFuncAttributeMaxDynamicSharedMemorySize,
                         ATT_SMEM_BYTES);

    // 0) round weights to fp16 once per call
    wprep_kernel<<<dim3(E_DIM * E_DIM / 1024, 4), 256>>>(Wq, Wk, Wv, Wout);

    // 1) pre-norm (fp16 output) + rope table
    ln_kernel<<<T_TOK, 256>>>(x, norm_w, norm_b, hh);
    rope_table_kernel<<<T_TOK / 8, 256>>>(cu, nb);

    // 2) merged Q/K/V projections (fp16 MMA; v straight to fp16)
    gemm_qkv<<<dim3(30, T_TOK / 128), 128, GEMM_SMEM_BYTES>>>(q, k);

    // 3) q/k LayerNorm + RoPE (q in-place fp32; k -> fp16)
    lnrope_kernel<<<dim3(T_TOK, 2), 256>>>(q, k, khp, lnq_w, lnk_w);

    // 4) attention (fp16 MMA, register-resident P)
    dim3 agrid(SEQ / 128, NHEAD, NBATCH);
    attn_f16<<<agrid, 128, ATT_SMEM_BYTES>>>(q, khp, vhp, oh);

    // 5) output projection (fp16 MMA)
    gemm_one<<<dim3(E_DIM / 128, T_TOK / 128), 128, GEMM_SMEM_BYTES>>>(out);
}

// round 17
// speedup vs baseline: 1.7969x; 1.0956x over previous
#include <cuda_runtime.h>
#include <cuda_fp16.h>
#include <math.h>

#define E_DIM 1280
#define NHEAD 20
#define DHEAD 64
#define T_TOK 8192
#define SEQ   1024
#define NBATCH 8

// ---------------- scratch (no allocations allowed) ----------------
__device__ __half g_hh[T_TOK * E_DIM];     // LN output (fp16)
__device__ float  g_q[T_TOK * E_DIM];      // q (fp32, RoPE'd in place)
__device__ float  g_k[T_TOK * E_DIM];      // k pre-LN (fp32, gemm out)
__device__ __half g_kh[T_TOK * E_DIM];     // k post-LN+RoPE (fp16)
__device__ __half g_vh[T_TOK * E_DIM];     // v (fp16, gemm out)
__device__ __half g_oh[T_TOK * E_DIM];     // attention output (fp16)
__device__ __half g_wqh[E_DIM * E_DIM];
__device__ __half g_wkh[E_DIM * E_DIM];
__device__ __half g_wvh[E_DIM * E_DIM];
__device__ __half g_woh[E_DIM * E_DIM];
__device__ float  g_cos[T_TOK * 32];
__device__ float  g_sin[T_TOK * 32];

// ---------------- helpers ----------------
__device__ __forceinline__ unsigned h2u(float a, float b) {
    __half2 t = __floats2half2_rn(a, b);
    return *(unsigned*)&t;
}

__device__ __forceinline__ void mma_f16(float c[4], const unsigned a[4],
                                        unsigned b0, unsigned b1) {
    asm volatile(
        "mma.sync.aligned.m16n8k16.row.col.f32.f16.f16.f32 "
        "{%0,%1,%2,%3}, {%4,%5,%6,%7}, {%8,%9}, {%0,%1,%2,%3};\n"
        : "+f"(c[0]), "+f"(c[1]), "+f"(c[2]), "+f"(c[3])
        : "r"(a[0]), "r"(a[1]), "r"(a[2]), "r"(a[3]), "r"(b0), "r"(b1));
}

__device__ __forceinline__ void ldsm_x4(unsigned r[4], unsigned addr) {
    asm volatile("ldmatrix.sync.aligned.m8n8.x4.shared.b16 {%0,%1,%2,%3}, [%4];"
                 : "=r"(r[0]), "=r"(r[1]), "=r"(r[2]), "=r"(r[3]) : "r"(addr));
}

__device__ __forceinline__ void ldsm_x2_t(unsigned& r0, unsigned& r1,
                                          unsigned addr) {
    asm volatile("ldmatrix.sync.aligned.m8n8.x2.trans.shared.b16 {%0,%1}, [%2];"
                 : "=r"(r0), "=r"(r1) : "r"(addr));
}

__device__ __forceinline__ void cpa16(void* s, const void* g) {
    unsigned saddr = (unsigned)__cvta_generic_to_shared(s);
    asm volatile("cp.async.ca.shared.global [%0], [%1], 16;\n"
                 :: "r"(saddr), "l"(g));
}
__device__ __forceinline__ void cpa16u(unsigned saddr, const void* g) {
    asm volatile("cp.async.ca.shared.global [%0], [%1], 16;\n"
                 :: "r"(saddr), "l"(g));
}
#define CP_COMMIT() asm volatile("cp.async.commit_group;\n" ::: "memory")
#define CP_WAIT(N)  asm volatile("cp.async.wait_group " #N ";\n" ::: "memory")

// ------------- weight prep: round to fp16 in global ---------------
__global__ void __launch_bounds__(256) wprep_kernel(
    const float* __restrict__ Wq, const float* __restrict__ Wk,
    const float* __restrict__ Wv, const float* __restrict__ Wo)
{
    const float* src = (blockIdx.y == 0) ? Wq : (blockIdx.y == 1) ? Wk :
                       (blockIdx.y == 2) ? Wv : Wo;
    __half* dst = (blockIdx.y == 0) ? g_wqh : (blockIdx.y == 1) ? g_wkh :
                  (blockIdx.y == 2) ? g_wvh : g_woh;
    int i = (blockIdx.x * 256 + threadIdx.x) * 4;
    float4 v = *(const float4*)&src[i];
    *(__half2*)&dst[i]     = __floats2half2_rn(v.x, v.y);
    *(__half2*)&dst[i + 2] = __floats2half2_rn(v.z, v.w);
}

// ---------------- LayerNorm (with bias) : x -> h (fp16) ------------
__global__ void __launch_bounds__(256) ln_kernel(
    const float* __restrict__ x, const float* __restrict__ w,
    const float* __restrict__ b, __half* __restrict__ out)
{
    int t = blockIdx.x;
    const float* xr = x + (size_t)t * E_DIM;
    float vals[5];
    float s = 0.f, s2 = 0.f;
#pragma unroll
    for (int j = 0; j < 5; j++) {
        float v = xr[threadIdx.x + j * 256];
        vals[j] = v; s += v; s2 += v * v;
    }
    __shared__ float red0[8], red1[8];
    int lane = threadIdx.x & 31, wid = threadIdx.x >> 5;
#pragma unroll
    for (int o = 16; o; o >>= 1) {
        s  += __shfl_xor_sync(0xffffffffu, s,  o);
        s2 += __shfl_xor_sync(0xffffffffu, s2, o);
    }
    if (lane == 0) { red0[wid] = s; red1[wid] = s2; }
    __syncthreads();
    float ts = 0.f, ts2 = 0.f;
#pragma unroll
    for (int j = 0; j < 8; j++) { ts += red0[j]; ts2 += red1[j]; }
    float mean = ts * (1.f / E_DIM);
    float var  = ts2 * (1.f / E_DIM) - mean * mean;
    float rstd = rsqrtf(var + 1e-5f);
    __half* orow = out + (size_t)t * E_DIM;
#pragma unroll
    for (int j = 0; j < 5; j++) {
        int idx = threadIdx.x + j * 256;
        orow[idx] = __float2half_rn((vals[j] - mean) * rstd * w[idx] + b[idx]);
    }
}

// ---------------- RoPE table: cos/sin per (token, freq) ------------
__global__ void __launch_bounds__(256) rope_table_kernel(
    const int* __restrict__ cu, int nb)
{
    int t = blockIdx.x * 8 + (threadIdx.x >> 5);
    int f = threadIdx.x & 31;
    int seg = 0;
    for (int bb = 1; bb < nb; bb++) if (t >= cu[bb]) seg = bb;
    float pos = (float)(t - cu[seg]);
    const float kfreq = -0.2878231366f; // -ln(10000)/32
    float ang = pos * __expf((float)f * kfreq);
    float sn, c;
    sincosf(ang, &sn, &c);
    g_cos[t * 32 + f] = c;
    g_sin[t * 32 + f] = sn;
}

// ------------- LayerNorm (no bias) + RoPE --------------------------
// part 0: q in-place fp32. part 1: k fp32 -> g_kh fp16.
__global__ void __launch_bounds__(256) lnrope_kernel(
    float* __restrict__ q, const float* __restrict__ k,
    __half* __restrict__ kh,
    const float* __restrict__ wq, const float* __restrict__ wk)
{
    int t = blockIdx.x;
    int part = blockIdx.y;
    __shared__ float sb[E_DIM];
    __shared__ float red0[8], red1[8];
    __shared__ float s_stats[2];
    int lane = threadIdx.x & 31, wid = threadIdx.x >> 5;

    const float* src = (part ? k : q) + (size_t)t * E_DIM;
    const float* w = part ? wk : wq;
    float s = 0.f, s2 = 0.f;
    for (int i = threadIdx.x; i < E_DIM; i += 256) {
        float v = src[i];
        sb[i] = v; s += v; s2 += v * v;
    }
#pragma unroll
    for (int o = 16; o; o >>= 1) {
        s  += __shfl_xor_sync(0xffffffffu, s,  o);
        s2 += __shfl_xor_sync(0xffffffffu, s2, o);
    }
    if (lane == 0) { red0[wid] = s; red1[wid] = s2; }
    __syncthreads();
    if (threadIdx.x == 0) {
        float ts = 0.f, ts2 = 0.f;
#pragma unroll
        for (int j = 0; j < 8; j++) { ts += red0[j]; ts2 += red1[j]; }
        float mean = ts * (1.f / E_DIM);
        float var  = ts2 * (1.f / E_DIM) - mean * mean;
        s_stats[0] = mean;
        s_stats[1] = rsqrtf(var + 1e-5f);
    }
    __syncthreads();
    float mean = s_stats[0], rstd = s_stats[1];
    for (int i = threadIdx.x; i < E_DIM; i += 256) {
        int ld = i & 63;
        float xn = (sb[i] - mean) * rstd * w[i];
        int pi = (ld < 32) ? (i + 32) : (i - 32);
        float pn = (sb[pi] - mean) * rstd * w[pi];
        int fi = ld & 31;
        float c  = g_cos[t * 32 + fi];
        float sn = g_sin[t * 32 + fi];
        float rot = (ld < 32) ? -pn : pn;
        float val = xn * c + rot * sn;
        if (part) kh[(size_t)t * E_DIM + i] = __float2half_rn(val);
        else      q[(size_t)t * E_DIM + i] = val;
    }
}

// ------------- fp16 GEMM core, 3-stage cp.async, ldmatrix ----------
// BM=BN=128, BK=16, 128 threads (4 warps 2x2, 64x64 warp tiles).
// Fragments via ldmatrix.x4: A one per mf, B one per nf-pair
// (8 ldmatrix vs 32 LDS.32 per warp-tile). Row stride 48B: the 8
// 16B-phases start at words {0,12,24,4,16,28,8,20} -> conflict-free.
#define HROW_B 48
#define HTILE_B (128 * HROW_B)                // 6144
#define HSTAGE_B (2 * HTILE_B)                // 12288
#define GEMM_SMEM_BYTES (3 * HSTAGE_B)        // 36864

__device__ __forceinline__ void gemm_body(
    const __half* __restrict__ A, const __half* __restrict__ B,
    float* __restrict__ Cf, __half* __restrict__ Ch,
    int bm, int bn, int N, int K)
{
    extern __shared__ char dynsm[];
    unsigned sb_u = (unsigned)__cvta_generic_to_shared(dynsm);

    int tid = threadIdx.x, lane = tid & 31, warp = tid >> 5;
    int gid = lane >> 2, tig = lane & 3;
    int wm = (warp >> 1) * 64, wn = (warp & 1) * 64;

    // ldmatrix per-lane address patterns (relative to stage base):
    // A x4 (mf): matrices (rows0-7,k0)(rows8-15,k0)(rows0-7,k8)(rows8-15,k8)
    unsigned aPat = (unsigned)((wm + (lane & 15)) * HROW_B + (lane >> 4) * 16);
    // B x4 (nf pair): (nf,k0)(nf,k8)(nf+1,k0)(nf+1,k8)
    unsigned bPat = (unsigned)(HTILE_B +
                    (wn + (lane >> 4) * 8 + (lane & 7)) * HROW_B +
                    ((lane >> 3) & 1) * 16);

    float acc[4][8][4];
#pragma unroll
    for (int i = 0; i < 4; i++)
#pragma unroll
        for (int j = 0; j < 8; j++)
#pragma unroll
            for (int l = 0; l < 4; l++) acc[i][j][l] = 0.f;

    int lr = tid >> 1;           // 0..63
    int hc = tid & 1;
    const __half* Ap = A + (size_t)(bm + lr) * K + hc * 8;
    const __half* Bp = B + (size_t)(bn + lr) * K + hc * 8;

#define ISSUE(S, K0) { \
    int s_ = (S); int k0_ = (K0); \
    unsigned as_ = sb_u + (unsigned)s_ * HSTAGE_B; \
    unsigned bs_ = as_ + HTILE_B; \
    _Pragma("unroll") \
    for (int ii = 0; ii < 2; ii++) { \
        unsigned ro_ = (unsigned)(lr + ii * 64) * HROW_B + (unsigned)hc * 16; \
        cpa16u(as_ + ro_, Ap + (size_t)ii * 64 * K + k0_); \
        cpa16u(bs_ + ro_, Bp + (size_t)ii * 64 * K + k0_); \
    } }

#define COMPUTE(S) { \
    unsigned stg_ = sb_u + (unsigned)(S) * HSTAGE_B; \
    unsigned af[4][4]; \
    _Pragma("unroll") \
    for (int mf = 0; mf < 4; mf++) \
        ldsm_x4(af[mf], stg_ + aPat + (unsigned)(mf * 16 * HROW_B)); \
    _Pragma("unroll") \
    for (int nfp = 0; nfp < 4; nfp++) { \
        unsigned bf[4]; \
        ldsm_x4(bf, stg_ + bPat + (unsigned)(nfp * 16 * HROW_B)); \
        _Pragma("unroll") \
        for (int mf = 0; mf < 4; mf++) { \
            mma_f16(acc[mf][2 * nfp + 0], af[mf], bf[0], bf[1]); \
            mma_f16(acc[mf][2 * nfp + 1], af[mf], bf[2], bf[3]); \
        } \
    } }

    int NT = K / 16;   // 80
    ISSUE(0, 0);  CP_COMMIT();
    ISSUE(1, 16); CP_COMMIT();
    int cs = 0;
    for (int i = 0; i < NT; i++) {
        CP_WAIT(1);
        __syncthreads();
        COMPUTE(cs);
        if (i + 2 < NT) {
            int ns = cs - 1; if (ns < 0) ns = 2;
            ISSUE(ns, (i + 2) * 16);
        }
        CP_COMMIT();
        cs = (cs == 2) ? 0 : cs + 1;
    }

#pragma unroll
    for (int mf = 0; mf < 4; mf++)
#pragma unroll
        for (int nf = 0; nf < 8; nf++) {
            int row = bm + wm + mf * 16 + gid;
            int col = bn + wn + nf * 8 + 2 * tig;
            if (Ch) {
                *(__half2*)&Ch[(size_t)row * N + col] =
                    __floats2half2_rn(acc[mf][nf][0], acc[mf][nf][1]);
                *(__half2*)&Ch[(size_t)(row + 8) * N + col] =
                    __floats2half2_rn(acc[mf][nf][2], acc[mf][nf][3]);
            } else {
                *(float2*)&Cf[(size_t)row * N + col] =
                    make_float2(acc[mf][nf][0], acc[mf][nf][1]);
                *(float2*)&Cf[(size_t)(row + 8) * N + col] =
                    make_float2(acc[mf][nf][2], acc[mf][nf][3]);
            }
        }
#undef ISSUE
#undef COMPUTE
}

// Merged QKV: q,k fp32 out; v fp16 out.
__global__ void __launch_bounds__(128, 3) gemm_qkv(
    float* __restrict__ q, float* __restrict__ k)
{
    int which = blockIdx.x / 10;
    int bn = (blockIdx.x % 10) * 128;
    int bm = blockIdx.y * 128;
    const __half* B = (which == 0) ? g_wqh : (which == 1) ? g_wkh : g_wvh;
    float* Cf = (which == 0) ? q : (which == 1) ? k : (float*)0;
    __half* Ch = (which == 2) ? g_vh : (__half*)0;
    gemm_body(g_hh, B, Cf, Ch, bm, bn, E_DIM, E_DIM);
}

// Output projection: A = g_oh, B = g_woh, fp32 out.
__global__ void __launch_bounds__(128, 3) gemm_one(float* __restrict__ C)
{
    gemm_body(g_oh, g_woh, C, (__half*)0,
              blockIdx.y * 128, blockIdx.x * 128, E_DIM, E_DIM);
}

// ------------- flash attention (R16 passing version) ---------------
#define KH_STRIDE 72
#define ATT_STAGE_H (2 * 64 * KH_STRIDE)        // K then V: 9216 halfs
#define ATT_SMEM_BYTES (2 * ATT_STAGE_H * 2)    // 36864 bytes

__global__ void __launch_bounds__(128) attn_f16(
    const float* __restrict__ q, const __half* __restrict__ kh,
    const __half* __restrict__ vh, __half* __restrict__ o)
{
    extern __shared__ __half smh[];

    int b = blockIdx.z, h = blockIdx.y, qt = blockIdx.x;
    int tid = threadIdx.x;
    int warp = tid >> 5, lane = tid & 31;
    int gid = lane >> 2, tig = lane & 3;
    int m0 = warp * 32;
    int tq0 = b * SEQ + qt * 128;

#define ATT_ISSUE(KT, S) { \
    int kt_ = (KT); \
    __half* Ks_ = smh + (S) * ATT_STAGE_H; \
    __half* Vs_ = Ks_ + 64 * KH_STRIDE; \
    int tk0_ = b * SEQ + kt_ * 64; \
    _Pragma("unroll") \
    for (int ii = 0; ii < 4; ii++) { \
        int idx_ = tid + ii * 128; \
        int r_ = idx_ >> 3, c8_ = (idx_ & 7) << 3; \
        const size_t goff_ = (size_t)(tk0_ + r_) * E_DIM + h * 64 + c8_; \
        cpa16(&Ks_[r_ * KH_STRIDE + c8_], &kh[goff_]); \
        cpa16(&Vs_[r_ * KH_STRIDE + c8_], &vh[goff_]); \
    } }

    ATT_ISSUE(0, 0); CP_COMMIT();

    unsigned qf[4][2][4];
#pragma unroll
    for (int mf = 0; mf < 2; mf++) {
        const float* qp = q + (size_t)(tq0 + m0 + mf * 16 + gid) * E_DIM + h * 64;
#pragma unroll
        for (int ks = 0; ks < 4; ks++) {
            int c = ks * 16 + 2 * tig;
            qf[ks][mf][0] = h2u(qp[c] * 0.125f, qp[c + 1] * 0.125f);
            qf[ks][mf][1] = h2u(qp[(size_t)8 * E_DIM + c] * 0.125f,
                                qp[(size_t)8 * E_DIM + c + 1] * 0.125f);
            qf[ks][mf][2] = h2u(qp[c + 8] * 0.125f, qp[c + 9] * 0.125f);
            qf[ks][mf][3] = h2u(qp[(size_t)8 * E_DIM + c + 8] * 0.125f,
                                qp[(size_t)8 * E_DIM + c + 9] * 0.125f);
        }
    }

    float mrow[2][2], lrow[2][2];
#pragma unroll
    for (int mf = 0; mf < 2; mf++) {
        mrow[mf][0] = -1e30f; mrow[mf][1] = -1e30f;
        lrow[mf][0] = 0.f;    lrow[mf][1] = 0.f;
    }
    float oc[2][8][4];
#pragma unroll
    for (int mf = 0; mf < 2; mf++)
#pragma unroll
        for (int j = 0; j < 8; j++)
#pragma unroll
            for (int l = 0; l < 4; l++) oc[mf][j][l] = 0.f;

    for (int kt = 0; kt < SEQ / 64; kt++) {
        int cur = kt & 1;
        __half* Ks = smh + cur * ATT_STAGE_H;
        __half* Vs = Ks + 64 * KH_STRIDE;

        CP_WAIT(0);
        __syncthreads();

        float sc[2][8][4];
#pragma unroll
        for (int mf = 0; mf < 2; mf++)
#pragma unroll
            for (int j = 0; j < 8; j++)
#pragma unroll
                for (int l = 0; l < 4; l++) sc[mf][j][l] = 0.f;
#pragma unroll
        for (int ks = 0; ks < 4; ks++) {
#pragma unroll
            for (int nf = 0; nf < 8; nf++) {
                const __half* kr = &Ks[(nf * 8 + gid) * KH_STRIDE + ks * 16 + 2 * tig];
                unsigned b0 = *(const unsigned*)kr;
                unsigned b1 = *(const unsigned*)(kr + 8);
                mma_f16(sc[0][nf], qf[ks][0], b0, b1);
                mma_f16(sc[1][nf], qf[ks][1], b0, b1);
            }
        }

        unsigned pa[2][4][4];
#pragma unroll
        for (int mf = 0; mf < 2; mf++) {
            float tm0 = -1e30f, tm1 = -1e30f;
#pragma unroll
            for (int nf = 0; nf < 8; nf++) {
                tm0 = fmaxf(tm0, fmaxf(sc[mf][nf][0], sc[mf][nf][1]));
                tm1 = fmaxf(tm1, fmaxf(sc[mf][nf][2], sc[mf][nf][3]));
            }
            tm0 = fmaxf(tm0, __shfl_xor_sync(0xffffffffu, tm0, 1));
            tm0 = fmaxf(tm0, __shfl_xor_sync(0xffffffffu, tm0, 2));
            tm1 = fmaxf(tm1, __shfl_xor_sync(0xffffffffu, tm1, 1));
            tm1 = fmaxf(tm1, __shfl_xor_sync(0xffffffffu, tm1, 2));
            float mn0 = fmaxf(mrow[mf][0], tm0), mn1 = fmaxf(mrow[mf][1], tm1);
            float cor0 = __expf(mrow[mf][0] - mn0);
            float cor1 = __expf(mrow[mf][1] - mn1);
            float ls0 = 0.f, ls1 = 0.f;
#pragma unroll
            for (int nf = 0; nf < 8; nf++) {
                float p0 = __expf(sc[mf][nf][0] - mn0);
                float p1 = __expf(sc[mf][nf][1] - mn0);
                float p2 = __expf(sc[mf][nf][2] - mn1);
                float p3 = __expf(sc[mf][nf][3] - mn1);
                ls0 += p0 + p1; ls1 += p2 + p3;
                int ks_ = nf >> 1;
                if ((nf & 1) == 0) {
                    pa[mf][ks_][0] = h2u(p0, p1);
                    pa[mf][ks_][1] = h2u(p2, p3);
                } else {
                    pa[mf][ks_][2] = h2u(p0, p1);
                    pa[mf][ks_][3] = h2u(p2, p3);
                }
            }
            ls0 += __shfl_xor_sync(0xffffffffu, ls0, 1);
            ls0 += __shfl_xor_sync(0xffffffffu, ls0, 2);
            ls1 += __shfl_xor_sync(0xffffffffu, ls1, 1);
            ls1 += __shfl_xor_sync(0xffffffffu, ls1, 2);
            lrow[mf][0] = lrow[mf][0] * cor0 + ls0;
            lrow[mf][1] = lrow[mf][1] * cor1 + ls1;
            mrow[mf][0] = mn0; mrow[mf][1] = mn1;
#pragma unroll
            for (int nf = 0; nf < 8; nf++) {
                oc[mf][nf][0] *= cor0; oc[mf][nf][1] *= cor0;
                oc[mf][nf][2] *= cor1; oc[mf][nf][3] *= cor1;
            }
        }

        unsigned vrow = (unsigned)__cvta_generic_to_shared(
                            Vs + (lane & 15) * KH_STRIDE);
#pragma unroll
        for (int ks = 0; ks < 4; ks++) {
#pragma unroll
            for (int nf = 0; nf < 8; nf++) {
                unsigned v0, v1;
                ldsm_x2_t(v0, v1,
                          vrow + (unsigned)(ks * 16 * KH_STRIDE + nf * 8) * 2);
                mma_f16(oc[0][nf], pa[0][ks], v0, v1);
                mma_f16(oc[1][nf], pa[1][ks], v0, v1);
            }
        }

        if (kt + 1 < SEQ / 64) { ATT_ISSUE(kt + 1, 1 - cur); }
        CP_COMMIT();
    }

#pragma unroll
    for (int mf = 0; mf < 2; mf++) {
        float il0 = 1.f / lrow[mf][0], il1 = 1.f / lrow[mf][1];
        int row = tq0 + m0 + mf * 16 + gid;
#pragma unroll
        for (int nf = 0; nf < 8; nf++) {
            int col = h * 64 + nf * 8 + 2 * tig;
            *(__half2*)&o[(size_t)row * E_DIM + col] =
                __floats2half2_rn(oc[mf][nf][0] * il0, oc[mf][nf][1] * il0);
            *(__half2*)&o[(size_t)(row + 8) * E_DIM + col] =
                __floats2half2_rn(oc[mf][nf][2] * il1, oc[mf][nf][3] * il1);
        }
    }
#undef ATT_ISSUE
}

// -------------------------------------------------------------------
extern "C" void kernel_launch(void* const* d_in, const int* in_sizes, int n_in,
                              void* d_out, int out_size)
{
    const float* x  = (const float*)d_in[0];
    const int*   cu = (const int*)d_in[1];
    int idx = 2;
    if (in_sizes[2] == 1) idx = 3;  // skip scalar max_len if present
    const float* norm_w = (const float*)d_in[idx++];
    const float* norm_b = (const float*)d_in[idx++];
    const float* Wq     = (const float*)d_in[idx++];
    const float* Wk     = (const float*)d_in[idx++];
    const float* Wv     = (const float*)d_in[idx++];
    const float* Wout   = (const float*)d_in[idx++];
    const float* lnq_w  = (const float*)d_in[idx++];
    const float* lnk_w  = (const float*)d_in[idx++];
    float* out = (float*)d_out;

    int nb = in_sizes[1] - 1;

    __half *hh, *khp, *vhp, *oh;
    float *q, *k;
    cudaGetSymbolAddress((void**)&hh, g_hh);
    cudaGetSymbolAddress((void**)&q, g_q);
    cudaGetSymbolAddress((void**)&k, g_k);
    cudaGetSymbolAddress((void**)&khp, g_kh);
    cudaGetSymbolAddress((void**)&vhp, g_vh);
    cudaGetSymbolAddress((void**)&oh, g_oh);

    cudaFuncSetAttribute(gemm_qkv, cudaFuncAttributeMaxDynamicSharedMemorySize,
                         GEMM_SMEM_BYTES);
    cudaFuncSetAttribute(gemm_one, cudaFuncAttributeMaxDynamicSharedMemorySize,
                         GEMM_SMEM_BYTES);
    cudaFuncSetAttribute(attn_f16, cudaFuncAttributeMaxDynamicSharedMemorySize,
                         ATT_SMEM_BYTES);

    // 0) round weights to fp16 once per call
    wprep_kernel<<<dim3(E_DIM * E_DIM / 1024, 4), 256>>>(Wq, Wk, Wv, Wout);

    // 1) pre-norm (fp16 output) + rope table
    ln_kernel<<<T_TOK, 256>>>(x, norm_w, norm_b, hh);
    rope_table_kernel<<<T_TOK / 8, 256>>>(cu, nb);

    // 2) merged Q/K/V projections (fp16 MMA + ldmatrix fragments)
    gemm_qkv<<<dim3(30, T_TOK / 128), 128, GEMM_SMEM_BYTES>>>(q, k);

    // 3) q/k LayerNorm + RoPE (q in-place fp32; k -> fp16)
    lnrope_kernel<<<dim3(T_TOK, 2), 256>>>(q, k, khp, lnq_w, lnk_w);

    // 4) attention (fp16 MMA, register-resident P)
    dim3 agrid(SEQ / 128, NHEAD, NBATCH);
    attn_f16<<<agrid, 128, ATT_SMEM_BYTES>>>(q, khp, vhp, oh);

    // 5) output projection (fp16 MMA + ldmatrix fragments)
    gemm_one<<<dim3(E_DIM / 128, T_TOK / 128), 128, GEMM_SMEM_BYTES>>>(out);
}